// round 7
// baseline (speedup 1.0000x reference)
#include <cuda_runtime.h>
#include <cuda_bf16.h>
#include <math.h>
#include <stdint.h>

// ---------------------------------------------------------------------------
// QuantumHybridCNN, bf16 m16n8k16 version, bank-conflict-free smem strides.
//  k_conv: conv1 (scalar fp32) + conv2 implicit GEMM (bf16 MMA). 8 smp/block.
//  k_fc:   fc GEMM M=64 N=64 K=1024 bf16 MMA + pre + tanh.
//  k_tail: per-sample 4-qubit circuit + post + sigmoid.
// Stride choices (u32 units): hp 41 (bank 9t+g), wp/Bs 66 (bank 2t+8g) --
// both bijective over the (gid,tid4) lane split; old 40/72 gave 4/8-way
// conflicts which saturated L1 (91.8%).
// ---------------------------------------------------------------------------

#define BMAX 32768
__device__ uint32_t g_h2p[(size_t)BMAX * 512];
__device__ float    g_qin[(size_t)BMAX * 4];

__device__ __forceinline__ uint32_t packbf(float lo, float hi) {
    __nv_bfloat162 h = __floats2bfloat162_rn(lo, hi);
    return *(uint32_t*)&h;
}

__device__ __forceinline__ void mma16(float d[4], const uint32_t a[4],
                                      uint32_t b0, uint32_t b1) {
    asm volatile(
        "mma.sync.aligned.m16n8k16.row.col.f32.bf16.bf16.f32 "
        "{%0,%1,%2,%3}, {%4,%5,%6,%7}, {%8,%9}, {%0,%1,%2,%3};"
        : "+f"(d[0]), "+f"(d[1]), "+f"(d[2]), "+f"(d[3])
        : "r"(a[0]), "r"(a[1]), "r"(a[2]), "r"(a[3]), "r"(b0), "r"(b1));
}

// ---------------------------------------------------------------------------
// Kernel 1: conv1 + conv2 (bf16 MMA). 8 samples/block, warp = sample.
// smem u32: xs 512 | hp 8*16*41 = 5248 | wp 48*66 = 3168 | bs 64  = 8992
// ---------------------------------------------------------------------------
#define CONV_OFF_HP 512
#define CONV_OFF_WP (512 + 5248)
#define CONV_OFF_BS (CONV_OFF_WP + 3168)
#define CONV_SMEM_U32 (CONV_OFF_BS + 64)

__global__ void __launch_bounds__(256, 3) k_conv(
    const float* __restrict__ x,
    const float* __restrict__ c1w, const float* __restrict__ c1b,
    const float* __restrict__ c2w, const float* __restrict__ c2b,
    uint32_t* __restrict__ h2p, int B)
{
    extern __shared__ float sm[];
    float*    xs = sm;                               // [8][64]
    uint32_t* hp = (uint32_t*)sm + CONV_OFF_HP;      // [8 warps][16 cp][41]
    uint32_t* wp = (uint32_t*)sm + CONV_OFF_WP;      // [48 kp][66]
    float*    bs = sm + CONV_OFF_BS;                 // [64]

    int tid = threadIdx.x;
    int lane = tid & 31, warp = tid >> 5;
    int gid = lane >> 2, tid4 = lane & 3;
    int b0 = blockIdx.x * 8;

    for (int i = tid; i < 512; i += 256) xs[i] = x[b0 * 64 + i];
    // conv2 weights, k = t*32+c, packed over channel pairs (c even, c+1)
    for (int i = tid; i < 3072; i += 256) {
        int kp = i >> 6, o = i & 63;
        int k = 2 * kp, t = k >> 5, c = k & 31;
        wp[kp * 66 + o] = packbf(c2w[o * 96 + c * 3 + t],
                                 c2w[o * 96 + (c + 1) * 3 + t]);
    }
    if (tid < 64) bs[tid] = c2b[tid];
    __syncthreads();

    // ---- conv1 + relu + pool, lane = channel; pack pairs via shfl ----
    {
        float cw0 = __ldg(&c1w[lane * 3 + 0]);
        float cw1 = __ldg(&c1w[lane * 3 + 1]);
        float cw2 = __ldg(&c1w[lane * 3 + 2]);
        float cbb = __ldg(&c1b[lane]);
        const float* xr = &xs[warp * 64];
        uint32_t* hw = hp + warp * 656;
        if (!(lane & 1)) {                           // zero padding cols 0, 33
            hw[(lane >> 1) * 41 + 0]  = 0u;
            hw[(lane >> 1) * 41 + 33] = 0u;
        }
        #pragma unroll
        for (int j = 0; j < 32; j++) {
            int p = 2 * j;
            float xm = (p == 0)  ? 0.0f : xr[p - 1];
            float xp = (p == 62) ? 0.0f : xr[p + 2];
            float y0 = fmaf(cw0, xm,    fmaf(cw1, xr[p],     fmaf(cw2, xr[p + 1], cbb)));
            float y1 = fmaf(cw0, xr[p], fmaf(cw1, xr[p + 1], fmaf(cw2, xp,        cbb)));
            float v = fmaxf(fmaxf(y0, y1), 0.0f);
            float pv = __shfl_xor_sync(0xffffffffu, v, 1);
            if (!(lane & 1)) hw[(lane >> 1) * 41 + j + 1] = packbf(v, pv);
        }
    }
    __syncwarp();

    // ---- conv2 MMA: M=32 pos, N=64 ch, K=96 (6 k16 steps) ----
    const uint32_t* hw = hp + warp * 656;
    float acc[2][8][4];
    #pragma unroll
    for (int mt = 0; mt < 2; mt++)
        #pragma unroll
        for (int nb = 0; nb < 8; nb++)
            #pragma unroll
            for (int q = 0; q < 4; q++) acc[mt][nb][q] = 0.0f;

    #pragma unroll
    for (int ks = 0; ks < 6; ks++) {
        int k0 = ks * 16;
        int t = k0 >> 5, cp0 = (k0 & 31) >> 1, kp0 = k0 >> 1;
        uint32_t a[2][4];
        #pragma unroll
        for (int mt = 0; mt < 2; mt++) {
            int col = mt * 16 + gid + t;             // position + t
            a[mt][0] = hw[(cp0 + tid4) * 41 + col];
            a[mt][1] = hw[(cp0 + tid4) * 41 + col + 8];
            a[mt][2] = hw[(cp0 + tid4 + 4) * 41 + col];
            a[mt][3] = hw[(cp0 + tid4 + 4) * 41 + col + 8];
        }
        #pragma unroll
        for (int nb = 0; nb < 8; nb++) {
            uint32_t bb0 = wp[(kp0 + tid4) * 66 + nb * 8 + gid];
            uint32_t bb1 = wp[(kp0 + tid4 + 4) * 66 + nb * 8 + gid];
            mma16(acc[0][nb], a[0], bb0, bb1);
            mma16(acc[1][nb], a[1], bb0, bb1);
        }
    }

    // ---- bias + relu + pool (shfl_xor 4) + pack bf16x2 -> h2p ----
    uint32_t* dst = &h2p[(size_t)(b0 + warp) * 512];
    #pragma unroll
    for (int mt = 0; mt < 2; mt++) {
        #pragma unroll
        for (int nb = 0; nb < 8; nb++) {
            int cb = nb * 8 + 2 * tid4;
            float bb0 = bs[cb], bb1 = bs[cb + 1];
            float v0 = fmaxf(acc[mt][nb][0] + bb0, 0.0f);
            float v1 = fmaxf(acc[mt][nb][1] + bb1, 0.0f);
            float v2 = fmaxf(acc[mt][nb][2] + bb0, 0.0f);
            float v3 = fmaxf(acc[mt][nb][3] + bb1, 0.0f);
            float q0 = __shfl_xor_sync(0xffffffffu, v0, 4);
            float q1 = __shfl_xor_sync(0xffffffffu, v1, 4);
            float q2 = __shfl_xor_sync(0xffffffffu, v2, 4);
            float q3 = __shfl_xor_sync(0xffffffffu, v3, 4);
            if (!(gid & 1)) {
                int j0 = mt * 8 + (gid >> 1);
                int j1 = j0 + 4;
                dst[(j0 * 64 + cb) >> 1] = packbf(fmaxf(v0, q0), fmaxf(v1, q1));
                dst[(j1 * 64 + cb) >> 1] = packbf(fmaxf(v2, q2), fmaxf(v3, q3));
            }
        }
    }
}

// ---------------------------------------------------------------------------
// Kernel 2: fc GEMM M=64, N=64, K=1024 (bf16 MMA) + pre + tanh.
// 64 samples/block, grid 512. warp = (wm 0..3: m16, wn 0..1: n32).
// smem u32: As 64*36 | Bs 32*66 | Hs 64*65 f32 | prew 256 | fcb 64 | preb 4
// ---------------------------------------------------------------------------
#define FC_OFF_AS 0
#define FC_OFF_BS (64 * 36)
#define FC_OFF_HS (FC_OFF_BS + 32 * 66)
#define FC_OFF_PW (FC_OFF_HS + 64 * 65)
#define FC_OFF_FB (FC_OFF_PW + 256)
#define FC_OFF_PB (FC_OFF_FB + 64)
#define FC_SMEM_U32 (FC_OFF_PB + 4)

__global__ void __launch_bounds__(256, 4) k_fc(
    const uint32_t* __restrict__ h2p, const float* __restrict__ fcw,
    const float* __restrict__ fcb, const float* __restrict__ prew,
    const float* __restrict__ preb, float* __restrict__ qin_out, int B)
{
    extern __shared__ float sm[];
    uint32_t* As   = (uint32_t*)sm + FC_OFF_AS;   // [64][36]
    uint32_t* Bs   = (uint32_t*)sm + FC_OFF_BS;   // [32 kp][66]
    float* Hs      = sm + FC_OFF_HS;              // [64][65]
    float* s_prew  = sm + FC_OFF_PW;
    float* s_fcb   = sm + FC_OFF_FB;
    float* s_preb  = sm + FC_OFF_PB;

    int tid = threadIdx.x;
    int lane = tid & 31, warp = tid >> 5;
    int gid = lane >> 2, tid4 = lane & 3;
    int wm = warp & 3, wn = warp >> 2;
    int b0 = blockIdx.x * 64;

    s_prew[tid] = prew[tid];
    if (tid < 64) s_fcb[tid] = fcb[tid];
    if (tid < 4)  s_preb[tid] = preb[tid];

    float acc[4][4];
    #pragma unroll
    for (int nb = 0; nb < 4; nb++)
        #pragma unroll
        for (int q = 0; q < 4; q++) acc[nb][q] = 0.0f;

    // staging indices
    int a_r = tid >> 2, a_p = (tid & 3) * 8;           // A: row, kp offset
    int b_kp = tid >> 3, b_c = (tid & 7) * 8;          // B: kp row, col group
    const uint4* a_src = (const uint4*)&h2p[(size_t)(b0 + a_r) * 512 + a_p];

    uint4  pa0, pa1;
    float4 pb0, pb1, pb2, pb3;
    {   // prefetch chunk 0
        pa0 = a_src[0]; pa1 = a_src[1];
        int kpg = b_kp, k2 = 2 * kpg;
        int j = k2 >> 6, o = k2 & 63;
        const float4* r0 = (const float4*)&fcw[(o * 16 + j) * 64 + b_c];
        const float4* r1 = (const float4*)&fcw[((o + 1) * 16 + j) * 64 + b_c];
        pb0 = r0[0]; pb1 = r0[1]; pb2 = r1[0]; pb3 = r1[1];
    }

    for (int ch = 0; ch < 16; ch++) {
        __syncthreads();
        {   // store staged A
            uint32_t* d = &As[a_r * 36 + a_p];
            *(uint4*)d = pa0; *(uint4*)(d + 4) = pa1;
        }
        {   // pack + store staged B
            uint32_t* d = &Bs[b_kp * 66 + b_c];
            d[0] = packbf(pb0.x, pb2.x); d[1] = packbf(pb0.y, pb2.y);
            d[2] = packbf(pb0.z, pb2.z); d[3] = packbf(pb0.w, pb2.w);
            d[4] = packbf(pb1.x, pb3.x); d[5] = packbf(pb1.y, pb3.y);
            d[6] = packbf(pb1.z, pb3.z); d[7] = packbf(pb1.w, pb3.w);
        }
        __syncthreads();
        if (ch < 15) {   // prefetch next chunk
            pa0 = a_src[(ch + 1) * 8];
            pa1 = a_src[(ch + 1) * 8 + 1];
            int kpg = (ch + 1) * 32 + b_kp, k2 = 2 * kpg;
            int j = k2 >> 6, o = k2 & 63;
            const float4* r0 = (const float4*)&fcw[(o * 16 + j) * 64 + b_c];
            const float4* r1 = (const float4*)&fcw[((o + 1) * 16 + j) * 64 + b_c];
            pb0 = r0[0]; pb1 = r0[1]; pb2 = r1[0]; pb3 = r1[1];
        }

        #pragma unroll
        for (int ks = 0; ks < 4; ks++) {
            int kp0 = ks * 8;
            int r = wm * 16 + gid;
            uint32_t a[4];
            a[0] = As[r * 36 + kp0 + tid4];
            a[1] = As[(r + 8) * 36 + kp0 + tid4];
            a[2] = As[r * 36 + kp0 + tid4 + 4];
            a[3] = As[(r + 8) * 36 + kp0 + tid4 + 4];
            #pragma unroll
            for (int nb = 0; nb < 4; nb++) {
                uint32_t bb0 = Bs[(kp0 + tid4) * 66 + wn * 32 + nb * 8 + gid];
                uint32_t bb1 = Bs[(kp0 + tid4 + 4) * 66 + wn * 32 + nb * 8 + gid];
                mma16(acc[nb], a, bb0, bb1);
            }
        }
    }
    __syncthreads();

    // ---- bias + relu -> Hs ----
    #pragma unroll
    for (int nb = 0; nb < 4; nb++) {
        int r = wm * 16 + gid;
        int cb = wn * 32 + nb * 8 + 2 * tid4;
        float bb0 = s_fcb[cb], bb1 = s_fcb[cb + 1];
        Hs[r * 65 + cb]           = fmaxf(acc[nb][0] + bb0, 0.0f);
        Hs[r * 65 + cb + 1]       = fmaxf(acc[nb][1] + bb1, 0.0f);
        Hs[(r + 8) * 65 + cb]     = fmaxf(acc[nb][2] + bb0, 0.0f);
        Hs[(r + 8) * 65 + cb + 1] = fmaxf(acc[nb][3] + bb1, 0.0f);
    }
    __syncthreads();

    // ---- pre: 64 -> 4, tanh * pi/2 ----
    {
        int s = tid >> 2, wq = tid & 3;
        const float* h = &Hs[s * 65];
        float d = s_preb[wq];
        #pragma unroll 8
        for (int j = 0; j < 64; j++) d = fmaf(h[j], s_prew[j * 4 + wq], d);
        if (b0 + s < B)
            qin_out[(size_t)(b0 + s) * 4 + wq] = tanhf(d) * 1.5707963267948966f;
    }
}

// ---------------------------------------------------------------------------
// Kernel 3: per-sample 4-qubit circuit + post + sigmoid.
// ---------------------------------------------------------------------------
__device__ __forceinline__ void apply_ry(float st[16], float th, int mask)
{
    float s, c;
    sincosf(th * 0.5f, &s, &c);
    #pragma unroll
    for (int i = 0; i < 16; i++) {
        if (!(i & mask)) {
            int j = i | mask;
            float a = st[i], b = st[j];
            st[i] = c * a - s * b;
            st[j] = s * a + c * b;
        }
    }
}
__device__ __forceinline__ void apply_cnot(float st[16], int cm, int tm)
{
    #pragma unroll
    for (int i = 0; i < 16; i++) {
        if ((i & cm) && !(i & tm)) {
            int j = i | tm;
            float t = st[i]; st[i] = st[j]; st[j] = t;
        }
    }
}

__global__ __launch_bounds__(256) void k_tail(
    const float* __restrict__ qin, const float* __restrict__ qp,
    const float* __restrict__ postw, const float* __restrict__ postb,
    float* __restrict__ out, int B)
{
    __shared__ float s_qp[24], s_pw[4], s_pb[1];
    int tid = threadIdx.x;
    if (tid < 24) s_qp[tid] = qp[tid];
    if (tid < 4)  s_pw[tid] = postw[tid];
    if (tid == 0) s_pb[0]   = postb[0];
    __syncthreads();

    int b = blockIdx.x * 256 + tid;
    if (b >= B) return;

    float4 qv = *(const float4*)&qin[(size_t)b * 4];

    float st[16];
    #pragma unroll
    for (int i = 0; i < 16; i++) st[i] = 0.25f;
    apply_ry(st, qv.x, 8);
    apply_ry(st, qv.y, 4);
    apply_ry(st, qv.z, 2);
    apply_ry(st, qv.w, 1);
    for (int k = 0; k < 6; k++) {
        apply_cnot(st, 8, 4);
        apply_cnot(st, 2, 1);
        apply_cnot(st, 4, 2);
        apply_ry(st, s_qp[4 * k + 0], 8);
        apply_ry(st, s_qp[4 * k + 1], 4);
        apply_ry(st, s_qp[4 * k + 2], 2);
        apply_ry(st, s_qp[4 * k + 3], 1);
    }

    float z0 = 0.f, z1 = 0.f, z2 = 0.f, z3 = 0.f;
    #pragma unroll
    for (int i = 0; i < 16; i++) {
        float p = st[i] * st[i];
        z0 += (i & 8) ? -p : p;
        z1 += (i & 4) ? -p : p;
        z2 += (i & 2) ? -p : p;
        z3 += (i & 1) ? -p : p;
    }

    float t = s_pb[0];
    t = fmaf(z0, s_pw[0], t);
    t = fmaf(z1, s_pw[1], t);
    t = fmaf(z2, s_pw[2], t);
    t = fmaf(z3, s_pw[3], t);
    out[b] = 1.0f / (1.0f + expf(-t));
}

// ---------------------------------------------------------------------------
extern "C" void kernel_launch(void* const* d_in, const int* in_sizes, int n_in,
                              void* d_out, int out_size)
{
    const float* x       = (const float*)d_in[0];
    const float* conv1_w = (const float*)d_in[1];
    const float* conv1_b = (const float*)d_in[2];
    const float* conv2_w = (const float*)d_in[3];
    const float* conv2_b = (const float*)d_in[4];
    const float* fc_w    = (const float*)d_in[5];
    const float* fc_b    = (const float*)d_in[6];
    const float* pre_w   = (const float*)d_in[7];
    const float* pre_b   = (const float*)d_in[8];
    const float* q_par   = (const float*)d_in[9];
    const float* post_w  = (const float*)d_in[10];
    const float* post_b  = (const float*)d_in[11];
    float* out = (float*)d_out;

    int B = in_sizes[0] / 64;
    if (B > BMAX) B = BMAX;

    uint32_t* h2p;
    float* qin;
    cudaGetSymbolAddress((void**)&h2p, g_h2p);
    cudaGetSymbolAddress((void**)&qin, g_qin);

    size_t conv_sm = CONV_SMEM_U32 * 4;
    size_t fc_sm   = FC_SMEM_U32 * 4;
    cudaFuncSetAttribute(k_conv, cudaFuncAttributeMaxDynamicSharedMemorySize,
                         (int)conv_sm);
    cudaFuncSetAttribute(k_fc, cudaFuncAttributeMaxDynamicSharedMemorySize,
                         (int)fc_sm);

    k_conv<<<(B + 7) / 8, 256, conv_sm>>>(x, conv1_w, conv1_b, conv2_w,
                                          conv2_b, h2p, B);
    k_fc<<<(B + 63) / 64, 256, fc_sm>>>(h2p, fc_w, fc_b, pre_w, pre_b, qin, B);
    k_tail<<<(B + 255) / 256, 256>>>(qin, q_par, post_w, post_b, out, B);
}

// round 9
// speedup vs baseline: 1.2994x; 1.2994x over previous
#include <cuda_runtime.h>
#include <cuda_bf16.h>
#include <math.h>
#include <stdint.h>

// ---------------------------------------------------------------------------
// QuantumHybridCNN, bf16 MMA, transposed conv2 GEMM with register-resident
// weights + persistent conv blocks.
//  k_conv: loop over 4-sample tiles. conv1: warp = (sample, pos-half).
//          conv2: D[64ch][32pos] = W[64][96] @ P[96][32]; warp = (sample,
//          m-half); A (weights) in 48 persistent regs; pool in-thread.
//  h2p[b][q]: q = pos*32 + mtg*8 + gid, u32 = bf16x2(ch, ch+8),
//          ch = mtg*16+gid, pos = pooled position. fc permutes fcw to match.
//  k_fc:   fc GEMM M=64 N=64 K=1024 + pre + tanh. Bs col-major (stride 36).
//  k_tail: per-sample 4-qubit circuit + post + sigmoid.
// ---------------------------------------------------------------------------

#define BMAX 32768
__device__ uint32_t g_h2p[(size_t)BMAX * 512];
__device__ float    g_qin[(size_t)BMAX * 4];

__device__ __forceinline__ uint32_t packbf(float lo, float hi) {
    __nv_bfloat162 h = __floats2bfloat162_rn(lo, hi);
    return *(uint32_t*)&h;
}

__device__ __forceinline__ void mma16(float d[4], const uint32_t a[4],
                                      uint32_t b0, uint32_t b1) {
    asm volatile(
        "mma.sync.aligned.m16n8k16.row.col.f32.bf16.bf16.f32 "
        "{%0,%1,%2,%3}, {%4,%5,%6,%7}, {%8,%9}, {%0,%1,%2,%3};"
        : "+f"(d[0]), "+f"(d[1]), "+f"(d[2]), "+f"(d[3])
        : "r"(a[0]), "r"(a[1]), "r"(a[2]), "r"(a[3]), "r"(b0), "r"(b1));
}

// ---------------------------------------------------------------------------
// Kernel 1: conv1 + conv2, persistent. 256 threads, 2 blocks/SM, grid 296.
// smem u32: xs 256 | hp 4*16*40 = 2560 | wpT 48*72 = 3456 | bs 64
// ---------------------------------------------------------------------------
#define CV_HP 256
#define CV_WP (CV_HP + 2560)
#define CV_BS (CV_WP + 3456)
#define CV_SMEM_U32 (CV_BS + 64)
#define CONV_GRID 296

__global__ void __launch_bounds__(256, 2) k_conv(
    const float* __restrict__ x,
    const float* __restrict__ c1w, const float* __restrict__ c1b,
    const float* __restrict__ c2w, const float* __restrict__ c2b,
    uint32_t* __restrict__ h2p, int B, int ntiles)
{
    extern __shared__ float smf[];
    uint32_t* smu = (uint32_t*)smf;
    float*    xs  = smf;              // [4][64]
    uint32_t* hp  = smu + CV_HP;      // [4 samples][16 cp][40]
    uint32_t* wpT = smu + CV_WP;      // [48 kp][72]: bf16x2(W[ch][2kp],[2kp+1])
    float*    bs  = smf + CV_BS;      // [64]

    int tid = threadIdx.x;
    int lane = tid & 31, warp = tid >> 5;
    int gid = lane >> 2, tid4 = lane & 3;
    int sl = warp & 3;                // sample slot
    int mh = warp >> 2;               // m-half (channels) / pos-half (conv1)

    // ---- one-time staging: conv2 weights (k = t*32+c), biases, hp padding ----
    for (int i = tid; i < 3072; i += 256) {
        int kp = i >> 6, ch = i & 63;
        int k = 2 * kp, t = k >> 5, c = k & 31;
        wpT[kp * 72 + ch] = packbf(c2w[ch * 96 + c * 3 + t],
                                   c2w[ch * 96 + (c + 1) * 3 + t]);
    }
    if (tid < 64) bs[tid] = c2b[tid];
    if (tid < 64) {                   // zero-pad hp cols 0 and 33 (once)
        int s = tid >> 4, cp = tid & 15;
        hp[s * 640 + cp * 40 + 0]  = 0u;
        hp[s * 640 + cp * 40 + 33] = 0u;
    }
    __syncthreads();

    // ---- persistent A fragments (weights) + bias registers ----
    uint32_t aReg[2][6][4];
    float biasReg[2][2];
    #pragma unroll
    for (int mt = 0; mt < 2; mt++) {
        int mtg = mh * 2 + mt;
        biasReg[mt][0] = bs[mtg * 16 + gid];
        biasReg[mt][1] = bs[mtg * 16 + gid + 8];
        #pragma unroll
        for (int ks = 0; ks < 6; ks++) {
            int kp0 = ks * 8;
            aReg[mt][ks][0] = wpT[(kp0 + tid4) * 72 + mtg * 16 + gid];
            aReg[mt][ks][1] = wpT[(kp0 + tid4) * 72 + mtg * 16 + gid + 8];
            aReg[mt][ks][2] = wpT[(kp0 + tid4 + 4) * 72 + mtg * 16 + gid];
            aReg[mt][ks][3] = wpT[(kp0 + tid4 + 4) * 72 + mtg * 16 + gid + 8];
        }
    }

    // conv1 weights: lane = channel
    float cw0 = __ldg(&c1w[lane * 3 + 0]);
    float cw1 = __ldg(&c1w[lane * 3 + 1]);
    float cw2 = __ldg(&c1w[lane * 3 + 2]);
    float cbb = __ldg(&c1b[lane]);

    for (int tile = blockIdx.x; tile < ntiles; tile += CONV_GRID) {
        int s4 = tile * 4;

        // stage x: 4 samples x 64 floats, one element per thread
        {
            int gi = s4 * 64 + tid;
            xs[tid] = (gi < B * 64) ? x[gi] : 0.0f;
        }
        __syncthreads();   // also: all prev-iter hp reads complete

        // ---- conv1 + relu + pool: sample sl, positions [mh*16, mh*16+16) ----
        {
            const float* xr = &xs[sl * 64];
            int cp = lane >> 1;
            uint32_t* hrow = hp + sl * 640;
            #pragma unroll
            for (int it = 0; it < 16; it++) {
                int j = mh * 16 + ((cp + it) & 15);   // staggered: STS conflict-free
                int p = 2 * j;
                float xm  = (p == 0)  ? 0.0f : xr[p - 1];
                float xp2 = (p == 62) ? 0.0f : xr[p + 2];
                float y0 = fmaf(cw0, xm,    fmaf(cw1, xr[p],     fmaf(cw2, xr[p + 1], cbb)));
                float y1 = fmaf(cw0, xr[p], fmaf(cw1, xr[p + 1], fmaf(cw2, xp2,       cbb)));
                float v = fmaxf(fmaxf(y0, y1), 0.0f);
                float pv = __shfl_xor_sync(0xffffffffu, v, 1);
                if (!(lane & 1)) hrow[cp * 40 + j + 1] = packbf(v, pv);
            }
        }
        __syncthreads();

        // ---- conv2 MMA: D[m32 ch][32 pos], A in regs, B from hp ----
        float acc[2][4][4];
        #pragma unroll
        for (int mt = 0; mt < 2; mt++)
            #pragma unroll
            for (int nb = 0; nb < 4; nb++) {
                acc[mt][nb][0] = biasReg[mt][0];
                acc[mt][nb][1] = biasReg[mt][0];
                acc[mt][nb][2] = biasReg[mt][1];
                acc[mt][nb][3] = biasReg[mt][1];
            }

        const uint32_t* hrow = hp + sl * 640;
        #pragma unroll
        for (int ks = 0; ks < 6; ks++) {
            int t = ks >> 1, cp0 = (ks & 1) * 8;
            uint32_t b0[4], b1[4];
            #pragma unroll
            for (int nb = 0; nb < 4; nb++) {
                int col = nb * 8 + gid + t;
                b0[nb] = hrow[(cp0 + tid4) * 40 + col];
                b1[nb] = hrow[(cp0 + tid4 + 4) * 40 + col];
            }
            #pragma unroll
            for (int mt = 0; mt < 2; mt++)
                #pragma unroll
                for (int nb = 0; nb < 4; nb++)
                    mma16(acc[mt][nb], aReg[mt][ks], b0[nb], b1[nb]);
        }

        // ---- epilogue: relu+pool in-thread, pack (ch, ch+8), store ----
        int b = s4 + sl;
        if (b < B) {
            uint32_t* dst = h2p + (size_t)b * 512;
            #pragma unroll
            for (int mt = 0; mt < 2; mt++) {
                int mtg = mh * 2 + mt;
                #pragma unroll
                for (int nb = 0; nb < 4; nb++) {
                    float plow  = fmaxf(fmaxf(acc[mt][nb][0], acc[mt][nb][1]), 0.0f);
                    float phigh = fmaxf(fmaxf(acc[mt][nb][2], acc[mt][nb][3]), 0.0f);
                    dst[(nb * 4 + tid4) * 32 + mtg * 8 + gid] = packbf(plow, phigh);
                }
            }
        }
    }
}

// ---------------------------------------------------------------------------
// Kernel 2: fc GEMM M=64, N=64, K=1024 (bf16 MMA) + pre + tanh.
// 64 samples/block, grid B/64. Bs col-major [64 cols][36].
// ---------------------------------------------------------------------------
#define FC_OFF_AS 0
#define FC_OFF_BS (64 * 36)
#define FC_OFF_HS (FC_OFF_BS + 64 * 36)
#define FC_OFF_PW (FC_OFF_HS + 64 * 65)
#define FC_OFF_FB (FC_OFF_PW + 256)
#define FC_OFF_PB (FC_OFF_FB + 64)
#define FC_SMEM_U32 (FC_OFF_PB + 4)

__global__ void __launch_bounds__(256, 4) k_fc(
    const uint32_t* __restrict__ h2p, const float* __restrict__ fcw,
    const float* __restrict__ fcb, const float* __restrict__ prew,
    const float* __restrict__ preb, float* __restrict__ qin_out, int B)
{
    extern __shared__ float sm[];
    uint32_t* As   = (uint32_t*)sm + FC_OFF_AS;   // [64 rows][36]
    uint32_t* Bs   = (uint32_t*)sm + FC_OFF_BS;   // [64 cols][36] col-major
    float* Hs      = sm + FC_OFF_HS;              // [64][65]
    float* s_prew  = sm + FC_OFF_PW;
    float* s_fcb   = sm + FC_OFF_FB;
    float* s_preb  = sm + FC_OFF_PB;

    int tid = threadIdx.x;
    int lane = tid & 31, warp = tid >> 5;
    int gid = lane >> 2, tid4 = lane & 3;
    int wm = warp & 3, wn = warp >> 2;
    int b0 = blockIdx.x * 64;

    s_prew[tid] = prew[tid];
    if (tid < 64) s_fcb[tid] = fcb[tid];
    if (tid < 4)  s_preb[tid] = preb[tid];

    float acc[4][4];
    #pragma unroll
    for (int nb = 0; nb < 4; nb++)
        #pragma unroll
        for (int q = 0; q < 4; q++) acc[nb][q] = 0.0f;

    // staging indices
    int a_r = tid >> 2, a_p = (tid & 3) * 8;      // A: row, kp offset
    int s_kp = tid & 31, s_cg = tid >> 5;         // B: kp, col group of 8
    const uint4* a_src = (const uint4*)&h2p[(size_t)(b0 + a_r) * 512 + a_p];

    uint4  pa0, pa1;
    float4 pl0, pl1, ph0, ph1;
    {   // prefetch chunk 0. q = cc*32 + s_kp: pos=cc, mtg=s_kp>>3, g=s_kp&7
        pa0 = a_src[0]; pa1 = a_src[1];
        int ch_lo = (s_kp >> 3) * 16 + (s_kp & 7);
        const float4* rl = (const float4*)&fcw[(ch_lo * 16 + 0) * 64 + s_cg * 8];
        const float4* rh = (const float4*)&fcw[((ch_lo + 8) * 16 + 0) * 64 + s_cg * 8];
        pl0 = rl[0]; pl1 = rl[1]; ph0 = rh[0]; ph1 = rh[1];
    }

    for (int cc = 0; cc < 16; cc++) {
        __syncthreads();
        {   // store staged A
            uint32_t* d = &As[a_r * 36 + a_p];
            *(uint4*)d = pa0; *(uint4*)(d + 4) = pa1;
        }
        {   // pack + store staged B, col-major: Bs[col*36 + kp]
            float lo[8] = {pl0.x, pl0.y, pl0.z, pl0.w, pl1.x, pl1.y, pl1.z, pl1.w};
            float hi[8] = {ph0.x, ph0.y, ph0.z, ph0.w, ph1.x, ph1.y, ph1.z, ph1.w};
            #pragma unroll
            for (int j = 0; j < 8; j++)
                Bs[(s_cg * 8 + j) * 36 + s_kp] = packbf(lo[j], hi[j]);
        }
        __syncthreads();
        if (cc < 16 - 1) {   // prefetch next chunk
            pa0 = a_src[(cc + 1) * 8];
            pa1 = a_src[(cc + 1) * 8 + 1];
            int pos = cc + 1;
            int ch_lo = (s_kp >> 3) * 16 + (s_kp & 7);
            const float4* rl = (const float4*)&fcw[(ch_lo * 16 + pos) * 64 + s_cg * 8];
            const float4* rh = (const float4*)&fcw[((ch_lo + 8) * 16 + pos) * 64 + s_cg * 8];
            pl0 = rl[0]; pl1 = rl[1]; ph0 = rh[0]; ph1 = rh[1];
        }

        #pragma unroll
        for (int ks = 0; ks < 4; ks++) {
            int kp0 = ks * 8;
            int r = wm * 16 + gid;
            uint32_t a[4];
            a[0] = As[r * 36 + kp0 + tid4];
            a[1] = As[(r + 8) * 36 + kp0 + tid4];
            a[2] = As[r * 36 + kp0 + tid4 + 4];
            a[3] = As[(r + 8) * 36 + kp0 + tid4 + 4];
            #pragma unroll
            for (int nb = 0; nb < 4; nb++) {
                int col = wn * 32 + nb * 8 + gid;
                uint32_t bb0 = Bs[col * 36 + kp0 + tid4];
                uint32_t bb1 = Bs[col * 36 + kp0 + tid4 + 4];
                mma16(acc[nb], a, bb0, bb1);
            }
        }
    }
    __syncthreads();

    // ---- bias + relu -> Hs ----
    #pragma unroll
    for (int nb = 0; nb < 4; nb++) {
        int r = wm * 16 + gid;
        int cb = wn * 32 + nb * 8 + 2 * tid4;
        float bb0 = s_fcb[cb], bb1 = s_fcb[cb + 1];
        Hs[r * 65 + cb]           = fmaxf(acc[nb][0] + bb0, 0.0f);
        Hs[r * 65 + cb + 1]       = fmaxf(acc[nb][1] + bb1, 0.0f);
        Hs[(r + 8) * 65 + cb]     = fmaxf(acc[nb][2] + bb0, 0.0f);
        Hs[(r + 8) * 65 + cb + 1] = fmaxf(acc[nb][3] + bb1, 0.0f);
    }
    __syncthreads();

    // ---- pre: 64 -> 4, tanh * pi/2 ----
    {
        int s = tid >> 2, wq = tid & 3;
        const float* h = &Hs[s * 65];
        float d = s_preb[wq];
        #pragma unroll 8
        for (int j = 0; j < 64; j++) d = fmaf(h[j], s_prew[j * 4 + wq], d);
        if (b0 + s < B)
            qin_out[(size_t)(b0 + s) * 4 + wq] = tanhf(d) * 1.5707963267948966f;
    }
}

// ---------------------------------------------------------------------------
// Kernel 3: per-sample 4-qubit circuit + post + sigmoid.
// ---------------------------------------------------------------------------
__device__ __forceinline__ void apply_ry(float st[16], float th, int mask)
{
    float s, c;
    sincosf(th * 0.5f, &s, &c);
    #pragma unroll
    for (int i = 0; i < 16; i++) {
        if (!(i & mask)) {
            int j = i | mask;
            float a = st[i], b = st[j];
            st[i] = c * a - s * b;
            st[j] = s * a + c * b;
        }
    }
}
__device__ __forceinline__ void apply_cnot(float st[16], int cm, int tm)
{
    #pragma unroll
    for (int i = 0; i < 16; i++) {
        if ((i & cm) && !(i & tm)) {
            int j = i | tm;
            float t = st[i]; st[i] = st[j]; st[j] = t;
        }
    }
}

__global__ __launch_bounds__(256) void k_tail(
    const float* __restrict__ qin, const float* __restrict__ qp,
    const float* __restrict__ postw, const float* __restrict__ postb,
    float* __restrict__ out, int B)
{
    __shared__ float s_qp[24], s_pw[4], s_pb[1];
    int tid = threadIdx.x;
    if (tid < 24) s_qp[tid] = qp[tid];
    if (tid < 4)  s_pw[tid] = postw[tid];
    if (tid == 0) s_pb[0]   = postb[0];
    __syncthreads();

    int b = blockIdx.x * 256 + tid;
    if (b >= B) return;

    float4 qv = *(const float4*)&qin[(size_t)b * 4];

    float st[16];
    #pragma unroll
    for (int i = 0; i < 16; i++) st[i] = 0.25f;
    apply_ry(st, qv.x, 8);
    apply_ry(st, qv.y, 4);
    apply_ry(st, qv.z, 2);
    apply_ry(st, qv.w, 1);
    for (int k = 0; k < 6; k++) {
        apply_cnot(st, 8, 4);
        apply_cnot(st, 2, 1);
        apply_cnot(st, 4, 2);
        apply_ry(st, s_qp[4 * k + 0], 8);
        apply_ry(st, s_qp[4 * k + 1], 4);
        apply_ry(st, s_qp[4 * k + 2], 2);
        apply_ry(st, s_qp[4 * k + 3], 1);
    }

    float z0 = 0.f, z1 = 0.f, z2 = 0.f, z3 = 0.f;
    #pragma unroll
    for (int i = 0; i < 16; i++) {
        float p = st[i] * st[i];
        z0 += (i & 8) ? -p : p;
        z1 += (i & 4) ? -p : p;
        z2 += (i & 2) ? -p : p;
        z3 += (i & 1) ? -p : p;
    }

    float t = s_pb[0];
    t = fmaf(z0, s_pw[0], t);
    t = fmaf(z1, s_pw[1], t);
    t = fmaf(z2, s_pw[2], t);
    t = fmaf(z3, s_pw[3], t);
    out[b] = 1.0f / (1.0f + expf(-t));
}

// ---------------------------------------------------------------------------
extern "C" void kernel_launch(void* const* d_in, const int* in_sizes, int n_in,
                              void* d_out, int out_size)
{
    const float* x       = (const float*)d_in[0];
    const float* conv1_w = (const float*)d_in[1];
    const float* conv1_b = (const float*)d_in[2];
    const float* conv2_w = (const float*)d_in[3];
    const float* conv2_b = (const float*)d_in[4];
    const float* fc_w    = (const float*)d_in[5];
    const float* fc_b    = (const float*)d_in[6];
    const float* pre_w   = (const float*)d_in[7];
    const float* pre_b   = (const float*)d_in[8];
    const float* q_par   = (const float*)d_in[9];
    const float* post_w  = (const float*)d_in[10];
    const float* post_b  = (const float*)d_in[11];
    float* out = (float*)d_out;

    int B = in_sizes[0] / 64;
    if (B > BMAX) B = BMAX;
    int ntiles = (B + 3) / 4;

    uint32_t* h2p;
    float* qin;
    cudaGetSymbolAddress((void**)&h2p, g_h2p);
    cudaGetSymbolAddress((void**)&qin, g_qin);

    size_t conv_sm = CV_SMEM_U32 * 4;
    size_t fc_sm   = FC_SMEM_U32 * 4;
    cudaFuncSetAttribute(k_conv, cudaFuncAttributeMaxDynamicSharedMemorySize,
                         (int)conv_sm);
    cudaFuncSetAttribute(k_fc, cudaFuncAttributeMaxDynamicSharedMemorySize,
                         (int)fc_sm);

    k_conv<<<CONV_GRID, 256, conv_sm>>>(x, conv1_w, conv1_b, conv2_w, conv2_b,
                                        h2p, B, ntiles);
    k_fc<<<(B + 63) / 64, 256, fc_sm>>>(h2p, fc_w, fc_b, pre_w, pre_b, qin, B);
    k_tail<<<(B + 255) / 256, 256>>>(qin, q_par, post_w, post_b, out, B);
}

// round 10
// speedup vs baseline: 1.4909x; 1.1474x over previous
#include <cuda_runtime.h>
#include <cuda_bf16.h>
#include <math.h>
#include <stdint.h>

// ---------------------------------------------------------------------------
// QuantumHybridCNN, bf16 MMA, software-pipelined conv + fused fc/tail.
//  k_conv: persistent, double-buffered hp/xs; per tile one phase:
//          MMA(tile t) + conv1(tile t+G) + epilogue(t), ONE barrier/tile.
//          conv2 GEMM transposed: D[64ch][32pos], weights in registers.
//  h2p[b][q]: q = pos*32 + mtg*8 + gid, u32 = bf16x2(ch, ch+8).
//  k_fc:   fc GEMM M=64 N=64 K=1024 + pre + tanh + 4-qubit circuit + post
//          + sigmoid (tail fused; qin staged through smem).
// ---------------------------------------------------------------------------

#define BMAX 32768
__device__ uint32_t g_h2p[(size_t)BMAX * 512];

__device__ __forceinline__ uint32_t packbf(float lo, float hi) {
    __nv_bfloat162 h = __floats2bfloat162_rn(lo, hi);
    return *(uint32_t*)&h;
}

__device__ __forceinline__ void mma16(float d[4], const uint32_t a[4],
                                      uint32_t b0, uint32_t b1) {
    asm volatile(
        "mma.sync.aligned.m16n8k16.row.col.f32.bf16.bf16.f32 "
        "{%0,%1,%2,%3}, {%4,%5,%6,%7}, {%8,%9}, {%0,%1,%2,%3};"
        : "+f"(d[0]), "+f"(d[1]), "+f"(d[2]), "+f"(d[3])
        : "r"(a[0]), "r"(a[1]), "r"(a[2]), "r"(a[3]), "r"(b0), "r"(b1));
}

// ---------------------------------------------------------------------------
// Kernel 1: conv1 + conv2, persistent + pipelined. 256 thr, 2 blocks/SM.
// smem u32: xs 2*256 | hp 2*2560 | wpT 48*72=3456 | bs 64
// ---------------------------------------------------------------------------
#define CV_XS 0
#define CV_HP 512
#define CV_WP (CV_HP + 5120)
#define CV_BS (CV_WP + 3456)
#define CV_SMEM_U32 (CV_BS + 64)
#define CONV_GRID 296

__global__ void __launch_bounds__(256, 2) k_conv(
    const float* __restrict__ x,
    const float* __restrict__ c1w, const float* __restrict__ c1b,
    const float* __restrict__ c2w, const float* __restrict__ c2b,
    uint32_t* __restrict__ h2p, int B, int ntiles)
{
    extern __shared__ float smf[];
    uint32_t* smu = (uint32_t*)smf;
    float*    xs  = smf + CV_XS;      // [2 buf][4 samples][64]
    uint32_t* hp  = smu + CV_HP;      // [2 buf][4 samples][16 cp][40]
    uint32_t* wpT = smu + CV_WP;      // [48 kp][72]
    float*    bs  = smf + CV_BS;      // [64]

    int tid = threadIdx.x;
    int lane = tid & 31, warp = tid >> 5;
    int gid = lane >> 2, tid4 = lane & 3;
    int sl = warp & 3;                // sample slot
    int mh = warp >> 2;               // m-half (channels) / pos-half (conv1)

    // ---- one-time staging ----
    for (int i = tid; i < 3072; i += 256) {
        int kp = i >> 6, ch = i & 63;
        int k = 2 * kp, t = k >> 5, c = k & 31;
        wpT[kp * 72 + ch] = packbf(c2w[ch * 96 + c * 3 + t],
                                   c2w[ch * 96 + (c + 1) * 3 + t]);
    }
    if (tid < 64) bs[tid] = c2b[tid];
    if (tid < 128) {                  // zero-pad hp cols 0, 33 (both buffers)
        int bf = tid >> 6, s = (tid >> 4) & 3, cp = tid & 15;
        hp[bf * 2560 + s * 640 + cp * 40 + 0]  = 0u;
        hp[bf * 2560 + s * 640 + cp * 40 + 33] = 0u;
    }
    __syncthreads();

    // ---- persistent A fragments (weights) + bias registers ----
    uint32_t aReg[2][6][4];
    float biasReg[2][2];
    #pragma unroll
    for (int mt = 0; mt < 2; mt++) {
        int mtg = mh * 2 + mt;
        biasReg[mt][0] = bs[mtg * 16 + gid];
        biasReg[mt][1] = bs[mtg * 16 + gid + 8];
        #pragma unroll
        for (int ks = 0; ks < 6; ks++) {
            int kp0 = ks * 8;
            aReg[mt][ks][0] = wpT[(kp0 + tid4) * 72 + mtg * 16 + gid];
            aReg[mt][ks][1] = wpT[(kp0 + tid4) * 72 + mtg * 16 + gid + 8];
            aReg[mt][ks][2] = wpT[(kp0 + tid4 + 4) * 72 + mtg * 16 + gid];
            aReg[mt][ks][3] = wpT[(kp0 + tid4 + 4) * 72 + mtg * 16 + gid + 8];
        }
    }

    // conv1 weights: lane = channel
    float cw0 = __ldg(&c1w[lane * 3 + 0]);
    float cw1 = __ldg(&c1w[lane * 3 + 1]);
    float cw2 = __ldg(&c1w[lane * 3 + 2]);
    float cbb = __ldg(&c1b[lane]);
    int cp = lane >> 1;

    // ---- prologue: conv1 of first tile into buf 0 ----
    int tile0 = blockIdx.x;
    float xR;
    {
        int gi = tile0 * 256 + tid;
        xR = (tile0 < ntiles && gi < B * 64) ? x[gi] : 0.0f;
        xs[tid] = xR;                           // buf 0
    }
    __syncthreads();
    {
        const float* xr = &xs[sl * 64];
        uint32_t* hrow = hp + sl * 640;         // buf 0
        #pragma unroll
        for (int it = 0; it < 16; it++) {
            int j = mh * 16 + ((cp + it) & 15);
            int p = 2 * j;
            float xm  = (p == 0)  ? 0.0f : xr[p - 1];
            float xp2 = (p == 62) ? 0.0f : xr[p + 2];
            float y0 = fmaf(cw0, xm,    fmaf(cw1, xr[p],     fmaf(cw2, xr[p + 1], cbb)));
            float y1 = fmaf(cw0, xr[p], fmaf(cw1, xr[p + 1], fmaf(cw2, xp2,       cbb)));
            float v = fmaxf(fmaxf(y0, y1), 0.0f);
            float pv = __shfl_xor_sync(0xffffffffu, v, 1);
            if (!(lane & 1)) hrow[cp * 40 + j + 1] = packbf(v, pv);
        }
    }
    {   // prefetch x of tile0 + GRID
        int t1 = tile0 + CONV_GRID;
        int gi = t1 * 256 + tid;
        xR = (t1 < ntiles && gi < B * 64) ? x[gi] : 0.0f;
    }

    int buf = 0;
    for (int tile = tile0; tile < ntiles; tile += CONV_GRID) {
        // stage next tile's x into other buffer
        xs[(buf ^ 1) * 256 + tid] = xR;
        __syncthreads();   // hp[buf] conv1 done; xs[buf^1] visible

        // ---- MMA on hp[buf]: D[m32 ch][32 pos] ----
        float acc[2][4][4];
        #pragma unroll
        for (int mt = 0; mt < 2; mt++)
            #pragma unroll
            for (int nb = 0; nb < 4; nb++) {
                acc[mt][nb][0] = biasReg[mt][0];
                acc[mt][nb][1] = biasReg[mt][0];
                acc[mt][nb][2] = biasReg[mt][1];
                acc[mt][nb][3] = biasReg[mt][1];
            }
        {
            const uint32_t* hrow = hp + buf * 2560 + sl * 640;
            #pragma unroll
            for (int ks = 0; ks < 6; ks++) {
                int t = ks >> 1, cp0 = (ks & 1) * 8;
                uint32_t b0[4], b1[4];
                #pragma unroll
                for (int nb = 0; nb < 4; nb++) {
                    int col = nb * 8 + gid + t;
                    b0[nb] = hrow[(cp0 + tid4) * 40 + col];
                    b1[nb] = hrow[(cp0 + tid4 + 4) * 40 + col];
                }
                #pragma unroll
                for (int mt = 0; mt < 2; mt++)
                    #pragma unroll
                    for (int nb = 0; nb < 4; nb++)
                        mma16(acc[mt][nb], aReg[mt][ks], b0[nb], b1[nb]);
            }
        }

        // ---- conv1 of tile+GRID into hp[buf^1] (overlaps MMA across warps) ----
        {
            const float* xr = &xs[(buf ^ 1) * 256 + sl * 64];
            uint32_t* hrow = hp + (buf ^ 1) * 2560 + sl * 640;
            #pragma unroll
            for (int it = 0; it < 16; it++) {
                int j = mh * 16 + ((cp + it) & 15);
                int p = 2 * j;
                float xm  = (p == 0)  ? 0.0f : xr[p - 1];
                float xp2 = (p == 62) ? 0.0f : xr[p + 2];
                float y0 = fmaf(cw0, xm,    fmaf(cw1, xr[p],     fmaf(cw2, xr[p + 1], cbb)));
                float y1 = fmaf(cw0, xr[p], fmaf(cw1, xr[p + 1], fmaf(cw2, xp2,       cbb)));
                float v = fmaxf(fmaxf(y0, y1), 0.0f);
                float pv = __shfl_xor_sync(0xffffffffu, v, 1);
                if (!(lane & 1)) hrow[cp * 40 + j + 1] = packbf(v, pv);
            }
        }

        // ---- epilogue: relu+pool in-thread, pack (ch, ch+8), store ----
        {
            int b = tile * 4 + sl;
            if (b < B) {
                uint32_t* dst = h2p + (size_t)b * 512;
                #pragma unroll
                for (int mt = 0; mt < 2; mt++) {
                    int mtg = mh * 2 + mt;
                    #pragma unroll
                    for (int nb = 0; nb < 4; nb++) {
                        float plow  = fmaxf(fmaxf(acc[mt][nb][0], acc[mt][nb][1]), 0.0f);
                        float phigh = fmaxf(fmaxf(acc[mt][nb][2], acc[mt][nb][3]), 0.0f);
                        dst[(nb * 4 + tid4) * 32 + mtg * 8 + gid] = packbf(plow, phigh);
                    }
                }
            }
        }

        // ---- prefetch x of tile + 2*GRID ----
        {
            int t2 = tile + 2 * CONV_GRID;
            int gi = t2 * 256 + tid;
            xR = (t2 < ntiles && gi < B * 64) ? x[gi] : 0.0f;
        }
        buf ^= 1;
    }
}

// ---------------------------------------------------------------------------
// Quantum helpers (16 real amplitudes in registers).
// ---------------------------------------------------------------------------
__device__ __forceinline__ void apply_ry(float st[16], float th, int mask)
{
    float s, c;
    sincosf(th * 0.5f, &s, &c);
    #pragma unroll
    for (int i = 0; i < 16; i++) {
        if (!(i & mask)) {
            int j = i | mask;
            float a = st[i], b = st[j];
            st[i] = c * a - s * b;
            st[j] = s * a + c * b;
        }
    }
}
__device__ __forceinline__ void apply_cnot(float st[16], int cm, int tm)
{
    #pragma unroll
    for (int i = 0; i < 16; i++) {
        if ((i & cm) && !(i & tm)) {
            int j = i | tm;
            float t = st[i]; st[i] = st[j]; st[j] = t;
        }
    }
}

// ---------------------------------------------------------------------------
// Kernel 2: fc GEMM + pre + tanh + quantum circuit + post + sigmoid.
// 64 samples/block. Bs col-major [64 cols][36].
// ---------------------------------------------------------------------------
#define FC_OFF_AS 0
#define FC_OFF_BS (64 * 36)
#define FC_OFF_HS (FC_OFF_BS + 64 * 36)
#define FC_OFF_PW (FC_OFF_HS + 64 * 65)
#define FC_OFF_FB (FC_OFF_PW + 256)
#define FC_OFF_PB (FC_OFF_FB + 64)
#define FC_OFF_QP (FC_OFF_PB + 4)
#define FC_OFF_PO (FC_OFF_QP + 24)
#define FC_OFF_QS (FC_OFF_PO + 8)
#define FC_SMEM_U32 (FC_OFF_QS + 256)

__global__ void __launch_bounds__(256, 4) k_fc(
    const uint32_t* __restrict__ h2p, const float* __restrict__ fcw,
    const float* __restrict__ fcb, const float* __restrict__ prew,
    const float* __restrict__ preb, const float* __restrict__ qp,
    const float* __restrict__ postw, const float* __restrict__ postb,
    float* __restrict__ out, int B)
{
    extern __shared__ float sm[];
    uint32_t* As   = (uint32_t*)sm + FC_OFF_AS;   // [64 rows][36]
    uint32_t* Bs   = (uint32_t*)sm + FC_OFF_BS;   // [64 cols][36] col-major
    float* Hs      = sm + FC_OFF_HS;              // [64][65]
    float* s_prew  = sm + FC_OFF_PW;
    float* s_fcb   = sm + FC_OFF_FB;
    float* s_preb  = sm + FC_OFF_PB;
    float* s_qp    = sm + FC_OFF_QP;
    float* s_po    = sm + FC_OFF_PO;              // postw[0..3], postb[4]
    float* qs      = sm + FC_OFF_QS;              // [64][4] qin staging

    int tid = threadIdx.x;
    int lane = tid & 31, warp = tid >> 5;
    int gid = lane >> 2, tid4 = lane & 3;
    int wm = warp & 3, wn = warp >> 2;
    int b0 = blockIdx.x * 64;

    s_prew[tid] = prew[tid];
    if (tid < 64) s_fcb[tid] = fcb[tid];
    if (tid < 4)  s_preb[tid] = preb[tid];
    if (tid < 24) s_qp[tid] = qp[tid];
    if (tid >= 24 && tid < 28) s_po[tid - 24] = postw[tid - 24];
    if (tid == 28) s_po[4] = postb[0];

    float acc[4][4];
    #pragma unroll
    for (int nb = 0; nb < 4; nb++)
        #pragma unroll
        for (int q = 0; q < 4; q++) acc[nb][q] = 0.0f;

    // staging indices
    int a_r = tid >> 2, a_p = (tid & 3) * 8;      // A: row, kp offset
    int s_kp = tid & 31, s_cg = tid >> 5;         // B: kp, col group of 8
    const uint4* a_src = (const uint4*)&h2p[(size_t)(b0 + a_r) * 512 + a_p];

    uint4  pa0, pa1;
    float4 pl0, pl1, ph0, ph1;
    {   // prefetch chunk 0. q = cc*32 + s_kp: pos=cc, mtg=s_kp>>3, g=s_kp&7
        pa0 = a_src[0]; pa1 = a_src[1];
        int ch_lo = (s_kp >> 3) * 16 + (s_kp & 7);
        const float4* rl = (const float4*)&fcw[(ch_lo * 16 + 0) * 64 + s_cg * 8];
        const float4* rh = (const float4*)&fcw[((ch_lo + 8) * 16 + 0) * 64 + s_cg * 8];
        pl0 = rl[0]; pl1 = rl[1]; ph0 = rh[0]; ph1 = rh[1];
    }

    for (int cc = 0; cc < 16; cc++) {
        __syncthreads();
        {   // store staged A
            uint32_t* d = &As[a_r * 36 + a_p];
            *(uint4*)d = pa0; *(uint4*)(d + 4) = pa1;
        }
        {   // pack + store staged B, col-major: Bs[col*36 + kp]
            float lo[8] = {pl0.x, pl0.y, pl0.z, pl0.w, pl1.x, pl1.y, pl1.z, pl1.w};
            float hi[8] = {ph0.x, ph0.y, ph0.z, ph0.w, ph1.x, ph1.y, ph1.z, ph1.w};
            #pragma unroll
            for (int j = 0; j < 8; j++)
                Bs[(s_cg * 8 + j) * 36 + s_kp] = packbf(lo[j], hi[j]);
        }
        __syncthreads();
        if (cc < 15) {   // prefetch next chunk
            pa0 = a_src[(cc + 1) * 8];
            pa1 = a_src[(cc + 1) * 8 + 1];
            int pos = cc + 1;
            int ch_lo = (s_kp >> 3) * 16 + (s_kp & 7);
            const float4* rl = (const float4*)&fcw[(ch_lo * 16 + pos) * 64 + s_cg * 8];
            const float4* rh = (const float4*)&fcw[((ch_lo + 8) * 16 + pos) * 64 + s_cg * 8];
            pl0 = rl[0]; pl1 = rl[1]; ph0 = rh[0]; ph1 = rh[1];
        }

        #pragma unroll
        for (int ks = 0; ks < 4; ks++) {
            int kp0 = ks * 8;
            int r = wm * 16 + gid;
            uint32_t a[4];
            a[0] = As[r * 36 + kp0 + tid4];
            a[1] = As[(r + 8) * 36 + kp0 + tid4];
            a[2] = As[r * 36 + kp0 + tid4 + 4];
            a[3] = As[(r + 8) * 36 + kp0 + tid4 + 4];
            #pragma unroll
            for (int nb = 0; nb < 4; nb++) {
                int col = wn * 32 + nb * 8 + gid;
                uint32_t bb0 = Bs[col * 36 + kp0 + tid4];
                uint32_t bb1 = Bs[col * 36 + kp0 + tid4 + 4];
                mma16(acc[nb], a, bb0, bb1);
            }
        }
    }
    __syncthreads();

    // ---- bias + relu -> Hs ----
    #pragma unroll
    for (int nb = 0; nb < 4; nb++) {
        int r = wm * 16 + gid;
        int cb = wn * 32 + nb * 8 + 2 * tid4;
        float bb0 = s_fcb[cb], bb1 = s_fcb[cb + 1];
        Hs[r * 65 + cb]           = fmaxf(acc[nb][0] + bb0, 0.0f);
        Hs[r * 65 + cb + 1]       = fmaxf(acc[nb][1] + bb1, 0.0f);
        Hs[(r + 8) * 65 + cb]     = fmaxf(acc[nb][2] + bb0, 0.0f);
        Hs[(r + 8) * 65 + cb + 1] = fmaxf(acc[nb][3] + bb1, 0.0f);
    }
    __syncthreads();

    // ---- pre: 64 -> 4, tanh * pi/2 -> qs ----
    {
        int s = tid >> 2, wq = tid & 3;
        const float* h = &Hs[s * 65];
        float d = s_preb[wq];
        #pragma unroll 8
        for (int j = 0; j < 64; j++) d = fmaf(h[j], s_prew[j * 4 + wq], d);
        qs[tid] = tanhf(d) * 1.5707963267948966f;
    }
    __syncthreads();

    // ---- quantum circuit + post + sigmoid: threads 0..63 ----
    if (tid < 64 && b0 + tid < B) {
        float q0 = qs[tid * 4 + 0], q1 = qs[tid * 4 + 1];
        float q2 = qs[tid * 4 + 2], q3 = qs[tid * 4 + 3];

        float st[16];
        #pragma unroll
        for (int i = 0; i < 16; i++) st[i] = 0.25f;
        apply_ry(st, q0, 8);
        apply_ry(st, q1, 4);
        apply_ry(st, q2, 2);
        apply_ry(st, q3, 1);
        for (int k = 0; k < 6; k++) {
            apply_cnot(st, 8, 4);
            apply_cnot(st, 2, 1);
            apply_cnot(st, 4, 2);
            apply_ry(st, s_qp[4 * k + 0], 8);
            apply_ry(st, s_qp[4 * k + 1], 4);
            apply_ry(st, s_qp[4 * k + 2], 2);
            apply_ry(st, s_qp[4 * k + 3], 1);
        }

        float z0 = 0.f, z1 = 0.f, z2 = 0.f, z3 = 0.f;
        #pragma unroll
        for (int i = 0; i < 16; i++) {
            float p = st[i] * st[i];
            z0 += (i & 8) ? -p : p;
            z1 += (i & 4) ? -p : p;
            z2 += (i & 2) ? -p : p;
            z3 += (i & 1) ? -p : p;
        }

        float t = s_po[4];
        t = fmaf(z0, s_po[0], t);
        t = fmaf(z1, s_po[1], t);
        t = fmaf(z2, s_po[2], t);
        t = fmaf(z3, s_po[3], t);
        out[b0 + tid] = 1.0f / (1.0f + expf(-t));
    }
}

// ---------------------------------------------------------------------------
extern "C" void kernel_launch(void* const* d_in, const int* in_sizes, int n_in,
                              void* d_out, int out_size)
{
    const float* x       = (const float*)d_in[0];
    const float* conv1_w = (const float*)d_in[1];
    const float* conv1_b = (const float*)d_in[2];
    const float* conv2_w = (const float*)d_in[3];
    const float* conv2_b = (const float*)d_in[4];
    const float* fc_w    = (const float*)d_in[5];
    const float* fc_b    = (const float*)d_in[6];
    const float* pre_w   = (const float*)d_in[7];
    const float* pre_b   = (const float*)d_in[8];
    const float* q_par   = (const float*)d_in[9];
    const float* post_w  = (const float*)d_in[10];
    const float* post_b  = (const float*)d_in[11];
    float* out = (float*)d_out;

    int B = in_sizes[0] / 64;
    if (B > BMAX) B = BMAX;
    int ntiles = (B + 3) / 4;

    uint32_t* h2p;
    cudaGetSymbolAddress((void**)&h2p, g_h2p);

    size_t conv_sm = CV_SMEM_U32 * 4;
    size_t fc_sm   = FC_SMEM_U32 * 4;
    cudaFuncSetAttribute(k_conv, cudaFuncAttributeMaxDynamicSharedMemorySize,
                         (int)conv_sm);
    cudaFuncSetAttribute(k_fc, cudaFuncAttributeMaxDynamicSharedMemorySize,
                         (int)fc_sm);

    k_conv<<<CONV_GRID, 256, conv_sm>>>(x, conv1_w, conv1_b, conv2_w, conv2_b,
                                        h2p, B, ntiles);
    k_fc<<<(B + 63) / 64, 256, fc_sm>>>(h2p, fc_w, fc_b, pre_w, pre_b, q_par,
                                        post_w, post_b, out, B);
}

// round 11
// speedup vs baseline: 1.9529x; 1.3099x over previous
#include <cuda_runtime.h>
#include <cuda_bf16.h>
#include <math.h>
#include <stdint.h>

// ---------------------------------------------------------------------------
// QuantumHybridCNN, bf16 MMA.
//  k_conv: persistent, double-buffered, pipelined conv1+conv2; conv1 now
//          shfl-free (thread owns a channel pair, packs in-register).
//  k_fc:   fc GEMM M=64 N=64 K=1024, DOUBLE-BUFFERED staging -> 1 barrier
//          per chunk, + pre + tanh + 4-qubit circuit + post + sigmoid.
// h2p[b][q]: q = pos*32 + mtg*8 + gid, u32 = bf16x2(ch, ch+8).
// ---------------------------------------------------------------------------

#define BMAX 32768
__device__ uint32_t g_h2p[(size_t)BMAX * 512];

__device__ __forceinline__ uint32_t packbf(float lo, float hi) {
    __nv_bfloat162 h = __floats2bfloat162_rn(lo, hi);
    return *(uint32_t*)&h;
}

__device__ __forceinline__ void mma16(float d[4], const uint32_t a[4],
                                      uint32_t b0, uint32_t b1) {
    asm volatile(
        "mma.sync.aligned.m16n8k16.row.col.f32.bf16.bf16.f32 "
        "{%0,%1,%2,%3}, {%4,%5,%6,%7}, {%8,%9}, {%0,%1,%2,%3};"
        : "+f"(d[0]), "+f"(d[1]), "+f"(d[2]), "+f"(d[3])
        : "r"(a[0]), "r"(a[1]), "r"(a[2]), "r"(a[3]), "r"(b0), "r"(b1));
}

// conv1 + relu + pool for one sample: thread owns channel pair (2cp, 2cp+1),
// positions sub*8..sub*8+7 within half mh. STS bank-conflict-free via m8 stagger.
__device__ __forceinline__ void conv1_phase(
    const float* __restrict__ xr, uint32_t* __restrict__ hrow,
    int cp, int sub, int mh, int m8,
    float wA0, float wA1, float wA2, float bA,
    float wB0, float wB1, float wB2, float bB)
{
    #pragma unroll
    for (int i = 0; i < 8; i++) {
        int o = (m8 + i) & 7;
        int j = mh * 16 + sub * 8 + o;
        int pp = 2 * j;
        float xm  = (pp == 0)  ? 0.0f : xr[pp - 1];
        float x0  = xr[pp], x1 = xr[pp + 1];
        float xp2 = (pp == 62) ? 0.0f : xr[pp + 2];
        float ya0 = fmaf(wA0, xm, fmaf(wA1, x0, fmaf(wA2, x1,  bA)));
        float ya1 = fmaf(wA0, x0, fmaf(wA1, x1, fmaf(wA2, xp2, bA)));
        float yb0 = fmaf(wB0, xm, fmaf(wB1, x0, fmaf(wB2, x1,  bB)));
        float yb1 = fmaf(wB0, x0, fmaf(wB1, x1, fmaf(wB2, xp2, bB)));
        float vA = fmaxf(fmaxf(ya0, ya1), 0.0f);
        float vB = fmaxf(fmaxf(yb0, yb1), 0.0f);
        hrow[cp * 40 + j + 1] = packbf(vA, vB);
    }
}

// ---------------------------------------------------------------------------
// Kernel 1: conv1 + conv2, persistent + pipelined. 256 thr, 2 blocks/SM.
// smem u32: xs 2*256 | hp 2*2560 | wpT 48*72=3456 | bs 64
// ---------------------------------------------------------------------------
#define CV_XS 0
#define CV_HP 512
#define CV_WP (CV_HP + 5120)
#define CV_BS (CV_WP + 3456)
#define CV_SMEM_U32 (CV_BS + 64)
#define CONV_GRID 296

__global__ void __launch_bounds__(256, 2) k_conv(
    const float* __restrict__ x,
    const float* __restrict__ c1w, const float* __restrict__ c1b,
    const float* __restrict__ c2w, const float* __restrict__ c2b,
    uint32_t* __restrict__ h2p, int B, int ntiles)
{
    extern __shared__ float smf[];
    uint32_t* smu = (uint32_t*)smf;
    float*    xs  = smf + CV_XS;      // [2 buf][4 samples][64]
    uint32_t* hp  = smu + CV_HP;      // [2 buf][4 samples][16 cp][40]
    uint32_t* wpT = smu + CV_WP;      // [48 kp][72]
    float*    bs  = smf + CV_BS;      // [64]

    int tid = threadIdx.x;
    int lane = tid & 31, warp = tid >> 5;
    int gid = lane >> 2, tid4 = lane & 3;
    int sl = warp & 3;                // sample slot
    int mh = warp >> 2;               // m-half (channels) / pos-half (conv1)

    // ---- one-time staging ----
    for (int i = tid; i < 3072; i += 256) {
        int kp = i >> 6, ch = i & 63;
        int k = 2 * kp, t = k >> 5, c = k & 31;
        wpT[kp * 72 + ch] = packbf(c2w[ch * 96 + c * 3 + t],
                                   c2w[ch * 96 + (c + 1) * 3 + t]);
    }
    if (tid < 64) bs[tid] = c2b[tid];
    if (tid < 128) {                  // zero-pad hp cols 0, 33 (both buffers)
        int bf = tid >> 6, s = (tid >> 4) & 3, cp = tid & 15;
        hp[bf * 2560 + s * 640 + cp * 40 + 0]  = 0u;
        hp[bf * 2560 + s * 640 + cp * 40 + 33] = 0u;
    }
    __syncthreads();

    // ---- persistent A fragments (weights) + bias registers ----
    uint32_t aReg[2][6][4];
    float biasReg[2][2];
    #pragma unroll
    for (int mt = 0; mt < 2; mt++) {
        int mtg = mh * 2 + mt;
        biasReg[mt][0] = bs[mtg * 16 + gid];
        biasReg[mt][1] = bs[mtg * 16 + gid + 8];
        #pragma unroll
        for (int ks = 0; ks < 6; ks++) {
            int kp0 = ks * 8;
            aReg[mt][ks][0] = wpT[(kp0 + tid4) * 72 + mtg * 16 + gid];
            aReg[mt][ks][1] = wpT[(kp0 + tid4) * 72 + mtg * 16 + gid + 8];
            aReg[mt][ks][2] = wpT[(kp0 + tid4 + 4) * 72 + mtg * 16 + gid];
            aReg[mt][ks][3] = wpT[(kp0 + tid4 + 4) * 72 + mtg * 16 + gid + 8];
        }
    }

    // conv1 weights: thread owns channel pair (2cp, 2cp+1)
    int cp = lane >> 1, sub = lane & 1;
    int m8 = (cp >> 2) + 4 * sub;     // bank-stagger id
    float wA0 = __ldg(&c1w[(2 * cp) * 3 + 0]);
    float wA1 = __ldg(&c1w[(2 * cp) * 3 + 1]);
    float wA2 = __ldg(&c1w[(2 * cp) * 3 + 2]);
    float bA  = __ldg(&c1b[2 * cp]);
    float wB0 = __ldg(&c1w[(2 * cp + 1) * 3 + 0]);
    float wB1 = __ldg(&c1w[(2 * cp + 1) * 3 + 1]);
    float wB2 = __ldg(&c1w[(2 * cp + 1) * 3 + 2]);
    float bB  = __ldg(&c1b[2 * cp + 1]);

    // ---- prologue: conv1 of first tile into buf 0 ----
    int tile0 = blockIdx.x;
    float xR;
    {
        int gi = tile0 * 256 + tid;
        xR = (tile0 < ntiles && gi < B * 64) ? x[gi] : 0.0f;
        xs[tid] = xR;                           // buf 0
    }
    __syncthreads();
    conv1_phase(&xs[sl * 64], hp + sl * 640, cp, sub, mh, m8,
                wA0, wA1, wA2, bA, wB0, wB1, wB2, bB);
    {   // prefetch x of tile0 + GRID
        int t1 = tile0 + CONV_GRID;
        int gi = t1 * 256 + tid;
        xR = (t1 < ntiles && gi < B * 64) ? x[gi] : 0.0f;
    }

    int buf = 0;
    for (int tile = tile0; tile < ntiles; tile += CONV_GRID) {
        // stage next tile's x into other buffer
        xs[(buf ^ 1) * 256 + tid] = xR;
        __syncthreads();   // hp[buf] conv1 done; xs[buf^1] visible

        // ---- MMA on hp[buf]: D[m32 ch][32 pos] ----
        float acc[2][4][4];
        #pragma unroll
        for (int mt = 0; mt < 2; mt++)
            #pragma unroll
            for (int nb = 0; nb < 4; nb++) {
                acc[mt][nb][0] = biasReg[mt][0];
                acc[mt][nb][1] = biasReg[mt][0];
                acc[mt][nb][2] = biasReg[mt][1];
                acc[mt][nb][3] = biasReg[mt][1];
            }
        {
            const uint32_t* hrow = hp + buf * 2560 + sl * 640;
            #pragma unroll
            for (int ks = 0; ks < 6; ks++) {
                int t = ks >> 1, cp0 = (ks & 1) * 8;
                uint32_t b0[4], b1[4];
                #pragma unroll
                for (int nb = 0; nb < 4; nb++) {
                    int col = nb * 8 + gid + t;
                    b0[nb] = hrow[(cp0 + tid4) * 40 + col];
                    b1[nb] = hrow[(cp0 + tid4 + 4) * 40 + col];
                }
                #pragma unroll
                for (int mt = 0; mt < 2; mt++)
                    #pragma unroll
                    for (int nb = 0; nb < 4; nb++)
                        mma16(acc[mt][nb], aReg[mt][ks], b0[nb], b1[nb]);
            }
        }

        // ---- conv1 of tile+GRID into hp[buf^1] (overlaps MMA across warps) ----
        conv1_phase(&xs[(buf ^ 1) * 256 + sl * 64],
                    hp + (buf ^ 1) * 2560 + sl * 640, cp, sub, mh, m8,
                    wA0, wA1, wA2, bA, wB0, wB1, wB2, bB);

        // ---- epilogue: relu+pool in-thread, pack (ch, ch+8), store ----
        {
            int b = tile * 4 + sl;
            if (b < B) {
                uint32_t* dst = h2p + (size_t)b * 512;
                #pragma unroll
                for (int mt = 0; mt < 2; mt++) {
                    int mtg = mh * 2 + mt;
                    #pragma unroll
                    for (int nb = 0; nb < 4; nb++) {
                        float plow  = fmaxf(fmaxf(acc[mt][nb][0], acc[mt][nb][1]), 0.0f);
                        float phigh = fmaxf(fmaxf(acc[mt][nb][2], acc[mt][nb][3]), 0.0f);
                        dst[(nb * 4 + tid4) * 32 + mtg * 8 + gid] = packbf(plow, phigh);
                    }
                }
            }
        }

        // ---- prefetch x of tile + 2*GRID ----
        {
            int t2 = tile + 2 * CONV_GRID;
            int gi = t2 * 256 + tid;
            xR = (t2 < ntiles && gi < B * 64) ? x[gi] : 0.0f;
        }
        buf ^= 1;
    }
}

// ---------------------------------------------------------------------------
// Quantum helpers (16 real amplitudes in registers).
// ---------------------------------------------------------------------------
__device__ __forceinline__ void apply_ry(float st[16], float th, int mask)
{
    float s, c;
    sincosf(th * 0.5f, &s, &c);
    #pragma unroll
    for (int i = 0; i < 16; i++) {
        if (!(i & mask)) {
            int j = i | mask;
            float a = st[i], b = st[j];
            st[i] = c * a - s * b;
            st[j] = s * a + c * b;
        }
    }
}
__device__ __forceinline__ void apply_cnot(float st[16], int cm, int tm)
{
    #pragma unroll
    for (int i = 0; i < 16; i++) {
        if ((i & cm) && !(i & tm)) {
            int j = i | tm;
            float t = st[i]; st[i] = st[j]; st[j] = t;
        }
    }
}

// ---------------------------------------------------------------------------
// Kernel 2: fc GEMM + pre + tanh + circuit + post + sigmoid.
// 64 samples/block. Double-buffered As/Bs, ONE barrier per chunk.
// ---------------------------------------------------------------------------
#define FC_OFF_AS 0
#define FC_OFF_BS (2 * 2304)
#define FC_OFF_HS (FC_OFF_BS + 2 * 2304)
#define FC_OFF_PW (FC_OFF_HS + 64 * 65)
#define FC_OFF_FB (FC_OFF_PW + 256)
#define FC_OFF_PB (FC_OFF_FB + 64)
#define FC_OFF_QP (FC_OFF_PB + 4)
#define FC_OFF_PO (FC_OFF_QP + 24)
#define FC_OFF_QS (FC_OFF_PO + 8)
#define FC_SMEM_U32 (FC_OFF_QS + 256)

__global__ void __launch_bounds__(256, 4) k_fc(
    const uint32_t* __restrict__ h2p, const float* __restrict__ fcw,
    const float* __restrict__ fcb, const float* __restrict__ prew,
    const float* __restrict__ preb, const float* __restrict__ qp,
    const float* __restrict__ postw, const float* __restrict__ postb,
    float* __restrict__ out, int B)
{
    extern __shared__ float sm[];
    uint32_t* As   = (uint32_t*)sm + FC_OFF_AS;   // [2][64 rows][36]
    uint32_t* Bs   = (uint32_t*)sm + FC_OFF_BS;   // [2][64 cols][36] col-major
    float* Hs      = sm + FC_OFF_HS;              // [64][65]
    float* s_prew  = sm + FC_OFF_PW;
    float* s_fcb   = sm + FC_OFF_FB;
    float* s_preb  = sm + FC_OFF_PB;
    float* s_qp    = sm + FC_OFF_QP;
    float* s_po    = sm + FC_OFF_PO;              // postw[0..3], postb[4]
    float* qs      = sm + FC_OFF_QS;              // [64][4] qin staging

    int tid = threadIdx.x;
    int lane = tid & 31, warp = tid >> 5;
    int gid = lane >> 2, tid4 = lane & 3;
    int wm = warp & 3, wn = warp >> 2;
    int b0 = blockIdx.x * 64;

    s_prew[tid] = prew[tid];
    if (tid < 64) s_fcb[tid] = fcb[tid];
    if (tid < 4)  s_preb[tid] = preb[tid];
    if (tid < 24) s_qp[tid] = qp[tid];
    if (tid >= 24 && tid < 28) s_po[tid - 24] = postw[tid - 24];
    if (tid == 28) s_po[4] = postb[0];

    float acc[4][4];
    #pragma unroll
    for (int nb = 0; nb < 4; nb++)
        #pragma unroll
        for (int q = 0; q < 4; q++) acc[nb][q] = 0.0f;

    // staging indices
    int a_r = tid >> 2, a_p = (tid & 3) * 8;      // A: row, kp offset
    int s_kp = tid & 31, s_cg = tid >> 5;         // B: kp, col group of 8
    const uint4* a_src = (const uint4*)&h2p[(size_t)(b0 + a_r) * 512 + a_p];
    int ch_lo = (s_kp >> 3) * 16 + (s_kp & 7);

    uint4  pa0, pa1;
    float4 pl0, pl1, ph0, ph1;
    {   // prefetch chunk 0
        pa0 = a_src[0]; pa1 = a_src[1];
        const float4* rl = (const float4*)&fcw[(ch_lo * 16 + 0) * 64 + s_cg * 8];
        const float4* rh = (const float4*)&fcw[((ch_lo + 8) * 16 + 0) * 64 + s_cg * 8];
        pl0 = rl[0]; pl1 = rl[1]; ph0 = rh[0]; ph1 = rh[1];
    }

    int p = 0;
    for (int cc = 0; cc < 16; cc++) {
        {   // store staged A into buffer p
            uint32_t* d = &As[p * 2304 + a_r * 36 + a_p];
            *(uint4*)d = pa0; *(uint4*)(d + 4) = pa1;
        }
        {   // pack + store staged B into buffer p (col-major)
            float lo[8] = {pl0.x, pl0.y, pl0.z, pl0.w, pl1.x, pl1.y, pl1.z, pl1.w};
            float hi[8] = {ph0.x, ph0.y, ph0.z, ph0.w, ph1.x, ph1.y, ph1.z, ph1.w};
            uint32_t* bb = &Bs[p * 2304];
            #pragma unroll
            for (int j = 0; j < 8; j++)
                bb[(s_cg * 8 + j) * 36 + s_kp] = packbf(lo[j], hi[j]);
        }
        __syncthreads();
        if (cc < 15) {   // prefetch next chunk (lands under this chunk's MMAs)
            pa0 = a_src[(cc + 1) * 8];
            pa1 = a_src[(cc + 1) * 8 + 1];
            int pos = cc + 1;
            const float4* rl = (const float4*)&fcw[(ch_lo * 16 + pos) * 64 + s_cg * 8];
            const float4* rh = (const float4*)&fcw[((ch_lo + 8) * 16 + pos) * 64 + s_cg * 8];
            pl0 = rl[0]; pl1 = rl[1]; ph0 = rh[0]; ph1 = rh[1];
        }

        #pragma unroll
        for (int ks = 0; ks < 4; ks++) {
            int kp0 = ks * 8;
            int r = wm * 16 + gid;
            const uint32_t* ab = &As[p * 2304];
            const uint32_t* bb = &Bs[p * 2304];
            uint32_t a[4];
            a[0] = ab[r * 36 + kp0 + tid4];
            a[1] = ab[(r + 8) * 36 + kp0 + tid4];
            a[2] = ab[r * 36 + kp0 + tid4 + 4];
            a[3] = ab[(r + 8) * 36 + kp0 + tid4 + 4];
            #pragma unroll
            for (int nb = 0; nb < 4; nb++) {
                int col = wn * 32 + nb * 8 + gid;
                uint32_t bb0 = bb[col * 36 + kp0 + tid4];
                uint32_t bb1 = bb[col * 36 + kp0 + tid4 + 4];
                mma16(acc[nb], a, bb0, bb1);
            }
        }
        p ^= 1;
    }

    // ---- bias + relu -> Hs ----
    #pragma unroll
    for (int nb = 0; nb < 4; nb++) {
        int r = wm * 16 + gid;
        int cb = wn * 32 + nb * 8 + 2 * tid4;
        float bb0 = s_fcb[cb], bb1 = s_fcb[cb + 1];
        Hs[r * 65 + cb]           = fmaxf(acc[nb][0] + bb0, 0.0f);
        Hs[r * 65 + cb + 1]       = fmaxf(acc[nb][1] + bb1, 0.0f);
        Hs[(r + 8) * 65 + cb]     = fmaxf(acc[nb][2] + bb0, 0.0f);
        Hs[(r + 8) * 65 + cb + 1] = fmaxf(acc[nb][3] + bb1, 0.0f);
    }
    __syncthreads();

    // ---- pre: 64 -> 4, tanh * pi/2 -> qs ----
    {
        int s = tid >> 2, wq = tid & 3;
        const float* h = &Hs[s * 65];
        float d = s_preb[wq];
        #pragma unroll 8
        for (int j = 0; j < 64; j++) d = fmaf(h[j], s_prew[j * 4 + wq], d);
        qs[tid] = tanhf(d) * 1.5707963267948966f;
    }
    __syncthreads();

    // ---- quantum circuit + post + sigmoid: threads 0..63 ----
    if (tid < 64 && b0 + tid < B) {
        float q0 = qs[tid * 4 + 0], q1 = qs[tid * 4 + 1];
        float q2 = qs[tid * 4 + 2], q3 = qs[tid * 4 + 3];

        float st[16];
        #pragma unroll
        for (int i = 0; i < 16; i++) st[i] = 0.25f;
        apply_ry(st, q0, 8);
        apply_ry(st, q1, 4);
        apply_ry(st, q2, 2);
        apply_ry(st, q3, 1);
        for (int k = 0; k < 6; k++) {
            apply_cnot(st, 8, 4);
            apply_cnot(st, 2, 1);
            apply_cnot(st, 4, 2);
            apply_ry(st, s_qp[4 * k + 0], 8);
            apply_ry(st, s_qp[4 * k + 1], 4);
            apply_ry(st, s_qp[4 * k + 2], 2);
            apply_ry(st, s_qp[4 * k + 3], 1);
        }

        float z0 = 0.f, z1 = 0.f, z2 = 0.f, z3 = 0.f;
        #pragma unroll
        for (int i = 0; i < 16; i++) {
            float pr = st[i] * st[i];
            z0 += (i & 8) ? -pr : pr;
            z1 += (i & 4) ? -pr : pr;
            z2 += (i & 2) ? -pr : pr;
            z3 += (i & 1) ? -pr : pr;
        }

        float t = s_po[4];
        t = fmaf(z0, s_po[0], t);
        t = fmaf(z1, s_po[1], t);
        t = fmaf(z2, s_po[2], t);
        t = fmaf(z3, s_po[3], t);
        out[b0 + tid] = 1.0f / (1.0f + expf(-t));
    }
}

// ---------------------------------------------------------------------------
extern "C" void kernel_launch(void* const* d_in, const int* in_sizes, int n_in,
                              void* d_out, int out_size)
{
    const float* x       = (const float*)d_in[0];
    const float* conv1_w = (const float*)d_in[1];
    const float* conv1_b = (const float*)d_in[2];
    const float* conv2_w = (const float*)d_in[3];
    const float* conv2_b = (const float*)d_in[4];
    const float* fc_w    = (const float*)d_in[5];
    const float* fc_b    = (const float*)d_in[6];
    const float* pre_w   = (const float*)d_in[7];
    const float* pre_b   = (const float*)d_in[8];
    const float* q_par   = (const float*)d_in[9];
    const float* post_w  = (const float*)d_in[10];
    const float* post_b  = (const float*)d_in[11];
    float* out = (float*)d_out;

    int B = in_sizes[0] / 64;
    if (B > BMAX) B = BMAX;
    int ntiles = (B + 3) / 4;

    uint32_t* h2p;
    cudaGetSymbolAddress((void**)&h2p, g_h2p);

    size_t conv_sm = CV_SMEM_U32 * 4;
    size_t fc_sm   = FC_SMEM_U32 * 4;
    cudaFuncSetAttribute(k_conv, cudaFuncAttributeMaxDynamicSharedMemorySize,
                         (int)conv_sm);
    cudaFuncSetAttribute(k_fc, cudaFuncAttributeMaxDynamicSharedMemorySize,
                         (int)fc_sm);

    k_conv<<<CONV_GRID, 256, conv_sm>>>(x, conv1_w, conv1_b, conv2_w, conv2_b,
                                        h2p, B, ntiles);
    k_fc<<<(B + 63) / 64, 256, fc_sm>>>(h2p, fc_w, fc_b, pre_w, pre_b, q_par,
                                        post_w, post_b, out, B);
}

// round 12
// speedup vs baseline: 2.2729x; 1.1639x over previous
#include <cuda_runtime.h>
#include <cuda_bf16.h>
#include <math.h>
#include <stdint.h>

// ---------------------------------------------------------------------------
// QuantumHybridCNN, bf16 MMA.
//  k_conv: persistent, double-buffered, pipelined conv1+conv2 (unchanged from
//          R11 winner) + one-time packing of fcw into g_fcwp streaming layout.
//  k_fc:   fc GEMM M=64 N=64 K=1024 with cp.async 3-stage ring (pure copies,
//          1 barrier/chunk, 2-chunk lead) + pre + tanh + circuit + sigmoid.
// h2p[b][q]: q = pos*32 + kp32, u32 = bf16x2(ch, ch+8), ch=(kp>>3)*16+(kp&7).
// g_fcwp[cc][kp][col] = bf16x2(fcw[(ch)*16+cc][col], fcw[(ch+8)*16+cc][col]).
// ---------------------------------------------------------------------------

#define BMAX 32768
__device__ uint32_t g_h2p[(size_t)BMAX * 512];
__device__ uint32_t g_fcwp[16 * 2048];

__device__ __forceinline__ uint32_t packbf(float lo, float hi) {
    __nv_bfloat162 h = __floats2bfloat162_rn(lo, hi);
    return *(uint32_t*)&h;
}

__device__ __forceinline__ void mma16(float d[4], const uint32_t a[4],
                                      uint32_t b0, uint32_t b1) {
    asm volatile(
        "mma.sync.aligned.m16n8k16.row.col.f32.bf16.bf16.f32 "
        "{%0,%1,%2,%3}, {%4,%5,%6,%7}, {%8,%9}, {%0,%1,%2,%3};"
        : "+f"(d[0]), "+f"(d[1]), "+f"(d[2]), "+f"(d[3])
        : "r"(a[0]), "r"(a[1]), "r"(a[2]), "r"(a[3]), "r"(b0), "r"(b1));
}

__device__ __forceinline__ void cpasync16(uint32_t smem_b, const void* g) {
    asm volatile("cp.async.ca.shared.global [%0], [%1], 16;"
                 :: "r"(smem_b), "l"(g));
}
__device__ __forceinline__ void cp_commit() {
    asm volatile("cp.async.commit_group;");
}
__device__ __forceinline__ void cp_wait1() {
    asm volatile("cp.async.wait_group 1;");
}

// conv1 + relu + pool (thread owns channel pair; STS staggered, conflict-free)
__device__ __forceinline__ void conv1_phase(
    const float* __restrict__ xr, uint32_t* __restrict__ hrow,
    int cp, int sub, int mh, int m8,
    float wA0, float wA1, float wA2, float bA,
    float wB0, float wB1, float wB2, float bB)
{
    #pragma unroll
    for (int i = 0; i < 8; i++) {
        int o = (m8 + i) & 7;
        int j = mh * 16 + sub * 8 + o;
        int pp = 2 * j;
        float xm  = (pp == 0)  ? 0.0f : xr[pp - 1];
        float x0  = xr[pp], x1 = xr[pp + 1];
        float xp2 = (pp == 62) ? 0.0f : xr[pp + 2];
        float ya0 = fmaf(wA0, xm, fmaf(wA1, x0, fmaf(wA2, x1,  bA)));
        float ya1 = fmaf(wA0, x0, fmaf(wA1, x1, fmaf(wA2, xp2, bA)));
        float yb0 = fmaf(wB0, xm, fmaf(wB1, x0, fmaf(wB2, x1,  bB)));
        float yb1 = fmaf(wB0, x0, fmaf(wB1, x1, fmaf(wB2, xp2, bB)));
        float vA = fmaxf(fmaxf(ya0, ya1), 0.0f);
        float vB = fmaxf(fmaxf(yb0, yb1), 0.0f);
        hrow[cp * 40 + j + 1] = packbf(vA, vB);
    }
}

// ---------------------------------------------------------------------------
// Kernel 1: conv1 + conv2, persistent + pipelined (R11) + fcw packing.
// ---------------------------------------------------------------------------
#define CV_XS 0
#define CV_HP 512
#define CV_WP (CV_HP + 5120)
#define CV_BS (CV_WP + 3456)
#define CV_SMEM_U32 (CV_BS + 64)
#define CONV_GRID 296

__global__ void __launch_bounds__(256, 2) k_conv(
    const float* __restrict__ x,
    const float* __restrict__ c1w, const float* __restrict__ c1b,
    const float* __restrict__ c2w, const float* __restrict__ c2b,
    const float* __restrict__ fcw,
    uint32_t* __restrict__ h2p, uint32_t* __restrict__ fcwp,
    int B, int ntiles)
{
    extern __shared__ float smf[];
    uint32_t* smu = (uint32_t*)smf;
    float*    xs  = smf + CV_XS;      // [2 buf][4 samples][64]
    uint32_t* hp  = smu + CV_HP;      // [2 buf][4 samples][16 cp][40]
    uint32_t* wpT = smu + CV_WP;      // [48 kp][72]
    float*    bs  = smf + CV_BS;      // [64]

    int tid = threadIdx.x;
    int lane = tid & 31, warp = tid >> 5;
    int gid = lane >> 2, tid4 = lane & 3;
    int sl = warp & 3;
    int mh = warp >> 2;

    // ---- one-time: pack fcw into streaming layout (1 u32 / thread) ----
    {
        int i = blockIdx.x * 256 + tid;
        if (i < 32768) {
            int cc = i >> 11, kp = (i >> 6) & 31, col = i & 63;
            int ch = ((kp >> 3) << 4) + (kp & 7);
            fcwp[i] = packbf(fcw[(ch * 16 + cc) * 64 + col],
                             fcw[((ch + 8) * 16 + cc) * 64 + col]);
        }
    }

    // ---- one-time staging ----
    for (int i = tid; i < 3072; i += 256) {
        int kp = i >> 6, ch = i & 63;
        int k = 2 * kp, t = k >> 5, c = k & 31;
        wpT[kp * 72 + ch] = packbf(c2w[ch * 96 + c * 3 + t],
                                   c2w[ch * 96 + (c + 1) * 3 + t]);
    }
    if (tid < 64) bs[tid] = c2b[tid];
    if (tid < 128) {
        int bf = tid >> 6, s = (tid >> 4) & 3, cp = tid & 15;
        hp[bf * 2560 + s * 640 + cp * 40 + 0]  = 0u;
        hp[bf * 2560 + s * 640 + cp * 40 + 33] = 0u;
    }
    __syncthreads();

    // ---- persistent A fragments (weights) + bias registers ----
    uint32_t aReg[2][6][4];
    float biasReg[2][2];
    #pragma unroll
    for (int mt = 0; mt < 2; mt++) {
        int mtg = mh * 2 + mt;
        biasReg[mt][0] = bs[mtg * 16 + gid];
        biasReg[mt][1] = bs[mtg * 16 + gid + 8];
        #pragma unroll
        for (int ks = 0; ks < 6; ks++) {
            int kp0 = ks * 8;
            aReg[mt][ks][0] = wpT[(kp0 + tid4) * 72 + mtg * 16 + gid];
            aReg[mt][ks][1] = wpT[(kp0 + tid4) * 72 + mtg * 16 + gid + 8];
            aReg[mt][ks][2] = wpT[(kp0 + tid4 + 4) * 72 + mtg * 16 + gid];
            aReg[mt][ks][3] = wpT[(kp0 + tid4 + 4) * 72 + mtg * 16 + gid + 8];
        }
    }

    int cp = lane >> 1, sub = lane & 1;
    int m8 = (cp >> 2) + 4 * sub;
    float wA0 = __ldg(&c1w[(2 * cp) * 3 + 0]);
    float wA1 = __ldg(&c1w[(2 * cp) * 3 + 1]);
    float wA2 = __ldg(&c1w[(2 * cp) * 3 + 2]);
    float bA  = __ldg(&c1b[2 * cp]);
    float wB0 = __ldg(&c1w[(2 * cp + 1) * 3 + 0]);
    float wB1 = __ldg(&c1w[(2 * cp + 1) * 3 + 1]);
    float wB2 = __ldg(&c1w[(2 * cp + 1) * 3 + 2]);
    float bB  = __ldg(&c1b[2 * cp + 1]);

    // ---- prologue ----
    int tile0 = blockIdx.x;
    float xR;
    {
        int gi = tile0 * 256 + tid;
        xR = (tile0 < ntiles && gi < B * 64) ? x[gi] : 0.0f;
        xs[tid] = xR;
    }
    __syncthreads();
    conv1_phase(&xs[sl * 64], hp + sl * 640, cp, sub, mh, m8,
                wA0, wA1, wA2, bA, wB0, wB1, wB2, bB);
    {
        int t1 = tile0 + CONV_GRID;
        int gi = t1 * 256 + tid;
        xR = (t1 < ntiles && gi < B * 64) ? x[gi] : 0.0f;
    }

    int buf = 0;
    for (int tile = tile0; tile < ntiles; tile += CONV_GRID) {
        xs[(buf ^ 1) * 256 + tid] = xR;
        __syncthreads();

        float acc[2][4][4];
        #pragma unroll
        for (int mt = 0; mt < 2; mt++)
            #pragma unroll
            for (int nb = 0; nb < 4; nb++) {
                acc[mt][nb][0] = biasReg[mt][0];
                acc[mt][nb][1] = biasReg[mt][0];
                acc[mt][nb][2] = biasReg[mt][1];
                acc[mt][nb][3] = biasReg[mt][1];
            }
        {
            const uint32_t* hrow = hp + buf * 2560 + sl * 640;
            #pragma unroll
            for (int ks = 0; ks < 6; ks++) {
                int t = ks >> 1, cp0 = (ks & 1) * 8;
                uint32_t b0[4], b1[4];
                #pragma unroll
                for (int nb = 0; nb < 4; nb++) {
                    int col = nb * 8 + gid + t;
                    b0[nb] = hrow[(cp0 + tid4) * 40 + col];
                    b1[nb] = hrow[(cp0 + tid4 + 4) * 40 + col];
                }
                #pragma unroll
                for (int mt = 0; mt < 2; mt++)
                    #pragma unroll
                    for (int nb = 0; nb < 4; nb++)
                        mma16(acc[mt][nb], aReg[mt][ks], b0[nb], b1[nb]);
            }
        }

        conv1_phase(&xs[(buf ^ 1) * 256 + sl * 64],
                    hp + (buf ^ 1) * 2560 + sl * 640, cp, sub, mh, m8,
                    wA0, wA1, wA2, bA, wB0, wB1, wB2, bB);

        {
            int b = tile * 4 + sl;
            if (b < B) {
                uint32_t* dst = h2p + (size_t)b * 512;
                #pragma unroll
                for (int mt = 0; mt < 2; mt++) {
                    int mtg = mh * 2 + mt;
                    #pragma unroll
                    for (int nb = 0; nb < 4; nb++) {
                        float plow  = fmaxf(fmaxf(acc[mt][nb][0], acc[mt][nb][1]), 0.0f);
                        float phigh = fmaxf(fmaxf(acc[mt][nb][2], acc[mt][nb][3]), 0.0f);
                        dst[(nb * 4 + tid4) * 32 + mtg * 8 + gid] = packbf(plow, phigh);
                    }
                }
            }
        }

        {
            int t2 = tile + 2 * CONV_GRID;
            int gi = t2 * 256 + tid;
            xR = (t2 < ntiles && gi < B * 64) ? x[gi] : 0.0f;
        }
        buf ^= 1;
    }
}

// ---------------------------------------------------------------------------
// Quantum helpers.
// ---------------------------------------------------------------------------
__device__ __forceinline__ void apply_ry(float st[16], float th, int mask)
{
    float s, c;
    sincosf(th * 0.5f, &s, &c);
    #pragma unroll
    for (int i = 0; i < 16; i++) {
        if (!(i & mask)) {
            int j = i | mask;
            float a = st[i], b = st[j];
            st[i] = c * a - s * b;
            st[j] = s * a + c * b;
        }
    }
}
__device__ __forceinline__ void apply_cnot(float st[16], int cm, int tm)
{
    #pragma unroll
    for (int i = 0; i < 16; i++) {
        if ((i & cm) && !(i & tm)) {
            int j = i | tm;
            float t = st[i]; st[i] = st[j]; st[j] = t;
        }
    }
}

// ---------------------------------------------------------------------------
// Kernel 2: fc GEMM (cp.async 3-stage ring) + pre + tanh + circuit + sigmoid.
// Stage layout (u32): As [64 rows][36] | Bs [32 kp][72]  = 4608 per stage.
// ---------------------------------------------------------------------------
#define FCS_STG 4608
#define FC_OFF_HS (3 * FCS_STG)
#define FC_OFF_PW (FC_OFF_HS + 64 * 65)
#define FC_OFF_FB (FC_OFF_PW + 256)
#define FC_OFF_PB (FC_OFF_FB + 64)
#define FC_OFF_QP (FC_OFF_PB + 4)
#define FC_OFF_PO (FC_OFF_QP + 24)
#define FC_OFF_QS (FC_OFF_PO + 8)
#define FC_SMEM_U32 (FC_OFF_QS + 256)

__global__ void __launch_bounds__(256, 3) k_fc(
    const uint32_t* __restrict__ h2p, const uint32_t* __restrict__ fcwp,
    const float* __restrict__ fcb, const float* __restrict__ prew,
    const float* __restrict__ preb, const float* __restrict__ qp,
    const float* __restrict__ postw, const float* __restrict__ postb,
    float* __restrict__ out, int B)
{
    extern __shared__ float sm[];
    uint32_t* smu  = (uint32_t*)sm;
    float* Hs      = sm + FC_OFF_HS;
    float* s_prew  = sm + FC_OFF_PW;
    float* s_fcb   = sm + FC_OFF_FB;
    float* s_preb  = sm + FC_OFF_PB;
    float* s_qp    = sm + FC_OFF_QP;
    float* s_po    = sm + FC_OFF_PO;
    float* qs      = sm + FC_OFF_QS;

    int tid = threadIdx.x;
    int lane = tid & 31, warp = tid >> 5;
    int gid = lane >> 2, tid4 = lane & 3;
    int wm = warp & 3, wn = warp >> 2;
    int b0 = blockIdx.x * 64;

    s_prew[tid] = prew[tid];
    if (tid < 64) s_fcb[tid] = fcb[tid];
    if (tid < 4)  s_preb[tid] = preb[tid];
    if (tid < 24) s_qp[tid] = qp[tid];
    if (tid >= 24 && tid < 28) s_po[tid - 24] = postw[tid - 24];
    if (tid == 28) s_po[4] = postb[0];

    float acc[4][4];
    #pragma unroll
    for (int nb = 0; nb < 4; nb++)
        #pragma unroll
        for (int q = 0; q < 4; q++) acc[nb][q] = 0.0f;

    uint32_t sbase = (uint32_t)__cvta_generic_to_shared(sm);

    // cp.async lane mapping (phase-exact, conflict-free):
    // A: quarter q4 = lane>>3, m = lane&7; row = warp*8+m; chunks q4, q4+4.
    int q4 = lane >> 3, m7 = lane & 7;
    int a_row = warp * 8 + m7;
    uint32_t aD0 = (uint32_t)(a_row * 36 + 4 * q4) * 4;
    uint32_t aD1 = (uint32_t)(a_row * 36 + 4 * (q4 + 4)) * 4;
    const uint32_t* a_g = h2p + (size_t)(b0 + a_row) * 512;
    // B: kp = warp*4 + (lane&3); col-chunk c = lane>>2, and c+8.
    int b_kp = warp * 4 + (lane & 3);
    int b_c  = lane >> 2;
    uint32_t bD0 = (uint32_t)(2304 + b_kp * 72 + 4 * b_c) * 4;
    uint32_t bD1 = (uint32_t)(2304 + b_kp * 72 + 4 * (b_c + 8)) * 4;
    const uint32_t* b_g = fcwp + b_kp * 64;

    #define FC_ISSUE(cc) do {                                              \
        uint32_t sb = sbase + (uint32_t)(((cc) % 3) * FCS_STG) * 4;        \
        cpasync16(sb + aD0, a_g + (cc) * 32 + 4 * q4);                     \
        cpasync16(sb + aD1, a_g + (cc) * 32 + 4 * (q4 + 4));               \
        cpasync16(sb + bD0, b_g + (cc) * 2048 + 4 * b_c);                  \
        cpasync16(sb + bD1, b_g + (cc) * 2048 + 4 * (b_c + 8));            \
    } while (0)

    FC_ISSUE(0); cp_commit();
    FC_ISSUE(1); cp_commit();

    for (int cc = 0; cc < 16; cc++) {
        cp_wait1();
        __syncthreads();
        if (cc + 2 < 16) FC_ISSUE(cc + 2);
        cp_commit();

        const uint32_t* ab = smu + (cc % 3) * FCS_STG;
        const uint32_t* bb = ab + 2304;
        #pragma unroll
        for (int ks = 0; ks < 4; ks++) {
            int kp0 = ks * 8;
            int r = wm * 16 + gid;
            uint32_t a[4];
            a[0] = ab[r * 36 + kp0 + tid4];
            a[1] = ab[(r + 8) * 36 + kp0 + tid4];
            a[2] = ab[r * 36 + kp0 + tid4 + 4];
            a[3] = ab[(r + 8) * 36 + kp0 + tid4 + 4];
            #pragma unroll
            for (int nb = 0; nb < 4; nb++) {
                int col = wn * 32 + nb * 8 + gid;
                uint32_t bb0 = bb[(kp0 + tid4) * 72 + col];
                uint32_t bb1 = bb[(kp0 + tid4 + 4) * 72 + col];
                mma16(acc[nb], a, bb0, bb1);
            }
        }
    }

    // ---- bias + relu -> Hs ----
    #pragma unroll
    for (int nb = 0; nb < 4; nb++) {
        int r = wm * 16 + gid;
        int cb = wn * 32 + nb * 8 + 2 * tid4;
        float bb0 = s_fcb[cb], bb1 = s_fcb[cb + 1];
        Hs[r * 65 + cb]           = fmaxf(acc[nb][0] + bb0, 0.0f);
        Hs[r * 65 + cb + 1]       = fmaxf(acc[nb][1] + bb1, 0.0f);
        Hs[(r + 8) * 65 + cb]     = fmaxf(acc[nb][2] + bb0, 0.0f);
        Hs[(r + 8) * 65 + cb + 1] = fmaxf(acc[nb][3] + bb1, 0.0f);
    }
    __syncthreads();

    // ---- pre: 64 -> 4, tanh * pi/2 -> qs ----
    {
        int s = tid >> 2, wq = tid & 3;
        const float* h = &Hs[s * 65];
        float d = s_preb[wq];
        #pragma unroll 8
        for (int j = 0; j < 64; j++) d = fmaf(h[j], s_prew[j * 4 + wq], d);
        qs[tid] = tanhf(d) * 1.5707963267948966f;
    }
    __syncthreads();

    // ---- quantum circuit + post + sigmoid: threads 0..63 ----
    if (tid < 64 && b0 + tid < B) {
        float q0 = qs[tid * 4 + 0], q1 = qs[tid * 4 + 1];
        float q2 = qs[tid * 4 + 2], q3 = qs[tid * 4 + 3];

        float st[16];
        #pragma unroll
        for (int i = 0; i < 16; i++) st[i] = 0.25f;
        apply_ry(st, q0, 8);
        apply_ry(st, q1, 4);
        apply_ry(st, q2, 2);
        apply_ry(st, q3, 1);
        for (int k = 0; k < 6; k++) {
            apply_cnot(st, 8, 4);
            apply_cnot(st, 2, 1);
            apply_cnot(st, 4, 2);
            apply_ry(st, s_qp[4 * k + 0], 8);
            apply_ry(st, s_qp[4 * k + 1], 4);
            apply_ry(st, s_qp[4 * k + 2], 2);
            apply_ry(st, s_qp[4 * k + 3], 1);
        }

        float z0 = 0.f, z1 = 0.f, z2 = 0.f, z3 = 0.f;
        #pragma unroll
        for (int i = 0; i < 16; i++) {
            float pr = st[i] * st[i];
            z0 += (i & 8) ? -pr : pr;
            z1 += (i & 4) ? -pr : pr;
            z2 += (i & 2) ? -pr : pr;
            z3 += (i & 1) ? -pr : pr;
        }

        float t = s_po[4];
        t = fmaf(z0, s_po[0], t);
        t = fmaf(z1, s_po[1], t);
        t = fmaf(z2, s_po[2], t);
        t = fmaf(z3, s_po[3], t);
        out[b0 + tid] = 1.0f / (1.0f + expf(-t));
    }
}

// ---------------------------------------------------------------------------
extern "C" void kernel_launch(void* const* d_in, const int* in_sizes, int n_in,
                              void* d_out, int out_size)
{
    const float* x       = (const float*)d_in[0];
    const float* conv1_w = (const float*)d_in[1];
    const float* conv1_b = (const float*)d_in[2];
    const float* conv2_w = (const float*)d_in[3];
    const float* conv2_b = (const float*)d_in[4];
    const float* fc_w    = (const float*)d_in[5];
    const float* fc_b    = (const float*)d_in[6];
    const float* pre_w   = (const float*)d_in[7];
    const float* pre_b   = (const float*)d_in[8];
    const float* q_par   = (const float*)d_in[9];
    const float* post_w  = (const float*)d_in[10];
    const float* post_b  = (const float*)d_in[11];
    float* out = (float*)d_out;

    int B = in_sizes[0] / 64;
    if (B > BMAX) B = BMAX;
    int ntiles = (B + 3) / 4;

    uint32_t* h2p;
    uint32_t* fcwp;
    cudaGetSymbolAddress((void**)&h2p, g_h2p);
    cudaGetSymbolAddress((void**)&fcwp, g_fcwp);

    size_t conv_sm = CV_SMEM_U32 * 4;
    size_t fc_sm   = FC_SMEM_U32 * 4;
    cudaFuncSetAttribute(k_conv, cudaFuncAttributeMaxDynamicSharedMemorySize,
                         (int)conv_sm);
    cudaFuncSetAttribute(k_fc, cudaFuncAttributeMaxDynamicSharedMemorySize,
                         (int)fc_sm);

    k_conv<<<CONV_GRID, 256, conv_sm>>>(x, conv1_w, conv1_b, conv2_w, conv2_b,
                                        fc_w, h2p, fcwp, B, ntiles);
    k_fc<<<(B + 63) / 64, 256, fc_sm>>>(h2p, fcwp, fc_b, pre_w, pre_b, q_par,
                                        post_w, post_b, out, B);
}